// round 11
// baseline (speedup 1.0000x reference)
#include <cuda_runtime.h>
#include <math.h>

#define NN 50000
#define NE 800000
#define IND 128

// ---------------- scratch ------------------------------------------------------
__device__ float g_hA[NN * 64];        // layer input (embed out / post-BN)
__device__ float g_hB[NN * 64];        // layer1 output (pre-BN)
__device__ float g_Hd[NN * 128];       // h @ preW_top  (dst half)
__device__ float g_Hs[NN * 128];       // h @ preW_bot  (src half) — 25.6MB, L2-resident
__device__ float g_agg[NN * 512];      // per node: [t][stat(mean,min,max,std)][f]
__device__ int   g_deg[NN];
__device__ float g_invc[NN];
__device__ float g_s1[NN];
__device__ float g_s2[NN];
__device__ int   g_rowptr[NN + 1];
__device__ int   g_cursor[NN];
__device__ int   g_csrc[NE];
__device__ float g_preB2a[64 * 256];   // layer1 packed preW  [k][c]
__device__ float g_preB2b[64 * 256];   // layer2 packed preW  [k][c]
__device__ float g_bnsum[64];
__device__ float g_bnsq[64];

// ---------------- setup --------------------------------------------------------
__global__ void k_init() {
    int i = blockIdx.x * blockDim.x + threadIdx.x;
    if (i < NN) g_deg[i] = 0;
    if (i < 64) { g_bnsum[i] = 0.f; g_bnsq[i] = 0.f; }
}

__global__ void k_degree(const int* __restrict__ dst) {
    int e = blockIdx.x * blockDim.x + threadIdx.x;
    if (e < NE) atomicAdd(&g_deg[dst[e]], 1);
}

// single block: log-mean reduction + prefix scan + per-node scales + cursor reset
__global__ void k_graph() {
    __shared__ int   ssum[1024];
    __shared__ float slog[1024];
    __shared__ float s_avg;
    const int CH = (NN + 1023) / 1024;   // 49
    int t  = threadIdx.x;
    int lo = t * CH, hi = min(lo + CH, NN);

    int s = 0; float lg = 0.f;
    for (int i = lo; i < hi; i++) {
        int d = g_deg[i];
        s += d;
        lg += logf((float)d + 1.f);
    }
    ssum[t] = s; slog[t] = lg;
    __syncthreads();

    // reduce slog
    for (int o = 512; o > 0; o >>= 1) {
        if (t < o) slog[t] += slog[t + o];
        __syncthreads();
    }
    if (t == 0) s_avg = slog[0] / (float)NN;

    // inclusive scan of ssum
    for (int o = 1; o < 1024; o <<= 1) {
        int v = (t >= o) ? ssum[t - o] : 0;
        __syncthreads();
        ssum[t] += v;
        __syncthreads();
    }
    float avg = s_avg;
    int run = (t == 0) ? 0 : ssum[t - 1];
    for (int i = lo; i < hi; i++) {
        g_rowptr[i] = run;
        int d = g_deg[i];
        run += d;
        g_cursor[i] = 0;
        float dc = fmaxf((float)d, 1.f);
        g_invc[i] = 1.f / dc;
        float ld = logf(dc + 1.f);
        g_s1[i] = ld / avg;
        g_s2[i] = avg / ld;
    }
    if (t == 1023) g_rowptr[NN] = ssum[1023];
}

__global__ void k_scatter(const int* __restrict__ src, const int* __restrict__ dst) {
    int e = blockIdx.x * blockDim.x + threadIdx.x;
    if (e >= NE) return;
    int d = dst[e];
    int pos = g_rowptr[d] + atomicAdd(&g_cursor[d], 1);
    g_csrc[pos] = src[e];
}

// pack both layers' preW (T,128,64) into [64][256]: col c: half=c>>7, j=c&127
__global__ void k_preB2both(const float* __restrict__ preW1,
                            const float* __restrict__ preW2) {
    int i = blockIdx.x * blockDim.x + threadIdx.x;
    if (i >= 2 * 64 * 256) return;
    int which = i >> 14;               // 0: layer1, 1: layer2
    int u = i & 16383;
    int k = u >> 8, c = u & 255;
    int half = c >> 7, j = c & 127;
    int t = j >> 6, f = j & 63;
    const float* w = which ? preW2 : preW1;
    float* o = which ? g_preB2b : g_preB2a;
    o[u] = w[t * 8192 + (half * 64 + k) * 64 + f];
}

// ---------------- embed GEMM: h = x @ W + b  (K=128, N=64) ----------------------
__global__ __launch_bounds__(256) void k_embed(const float* __restrict__ x,
                                               const float* __restrict__ W,
                                               const float* __restrict__ b) {
    __shared__ float Xs[128][64];
    __shared__ float Ws[128][64];
    int t  = threadIdx.x;
    int n0 = blockIdx.x * 64;

    for (int i = t; i < 2048; i += 256)
        ((float4*)Ws)[i] = ((const float4*)W)[i];

    int row = t & 63, kq = t >> 6;
    int gr = n0 + row;
#pragma unroll
    for (int j = 0; j < 8; j++) {
        int k = kq * 32 + j * 4;
        float4 v = make_float4(0.f, 0.f, 0.f, 0.f);
        if (gr < NN) v = *(const float4*)(x + (size_t)gr * IND + k);
        Xs[k][row] = v.x; Xs[k + 1][row] = v.y; Xs[k + 2][row] = v.z; Xs[k + 3][row] = v.w;
    }
    __syncthreads();

    int tx = t & 15, ty = t >> 4;
    float acc[4][4];
#pragma unroll
    for (int i = 0; i < 4; i++)
#pragma unroll
        for (int j = 0; j < 4; j++) acc[i][j] = 0.f;

#pragma unroll 8
    for (int k = 0; k < 128; k++) {
        float4 a  = *(const float4*)&Xs[k][ty * 4];
        float4 b4 = *(const float4*)&Ws[k][tx * 4];
        float ar[4] = {a.x, a.y, a.z, a.w};
        float br[4] = {b4.x, b4.y, b4.z, b4.w};
#pragma unroll
        for (int i = 0; i < 4; i++)
#pragma unroll
            for (int j = 0; j < 4; j++) acc[i][j] = fmaf(ar[i], br[j], acc[i][j]);
    }

    float4 bias = *(const float4*)(b + tx * 4);
#pragma unroll
    for (int i = 0; i < 4; i++) {
        int gn = n0 + ty * 4 + i;
        if (gn < NN) {
            float4 o = make_float4(acc[i][0] + bias.x, acc[i][1] + bias.y,
                                   acc[i][2] + bias.z, acc[i][3] + bias.w);
            *(float4*)(g_hA + (size_t)gn * 64 + tx * 4) = o;
        }
    }
}

// ---------------- Hd/Hs GEMM: [Hd|Hs] = h @ preB2  (K=64, N=256) ----------------
// layer==1: recomputes BN scale/shift in smem from g_bnsum/g_bnsq (replaces
// k_bnfin) and applies BN+ReLU to g_hB during the Xs load, writing g_hA.
__global__ __launch_bounds__(256) void k_hds(int layer,
                                             const float* __restrict__ gamma,
                                             const float* __restrict__ beta) {
    __shared__ float Xs[64][64];   // [k][node]
    __shared__ float Bs[64][64];   // [k][c]
    __shared__ float bsc[64], bsh[64];
    int t  = threadIdx.x;
    int n0 = blockIdx.x * 64;
    const float* preB = layer ? g_preB2b : g_preB2a;

    if (layer == 1) {
        if (t < 64) {
            float mu  = g_bnsum[t] / (float)NN;
            float var = g_bnsq[t] / (float)NN - mu * mu;
            float sc  = gamma[t] * rsqrtf(var + 1e-5f);
            bsc[t] = sc;
            bsh[t] = beta[t] - mu * sc;
        }
        __syncthreads();
    }

    int node = t & 63, kq = t >> 6;
    int gr = n0 + node;
#pragma unroll
    for (int j = 0; j < 4; j++) {
        int k = kq * 16 + j * 4;
        float4 v = make_float4(0.f, 0.f, 0.f, 0.f);
        if (gr < NN) {
            if (layer == 0) {
                v = *(const float4*)(g_hA + (size_t)gr * 64 + k);
            } else {
                float4 hv = *(const float4*)(g_hB + (size_t)gr * 64 + k);
                v.x = fmaxf(hv.x * bsc[k]     + bsh[k],     0.f);
                v.y = fmaxf(hv.y * bsc[k + 1] + bsh[k + 1], 0.f);
                v.z = fmaxf(hv.z * bsc[k + 2] + bsh[k + 2], 0.f);
                v.w = fmaxf(hv.w * bsc[k + 3] + bsh[k + 3], 0.f);
                *(float4*)(g_hA + (size_t)gr * 64 + k) = v;   // layer-2 h input
            }
        }
        Xs[k][node] = v.x; Xs[k + 1][node] = v.y; Xs[k + 2][node] = v.z; Xs[k + 3][node] = v.w;
    }

    int tx = t & 15, ty = t >> 4;

    for (int cg = 0; cg < 4; cg++) {
        __syncthreads();   // Xs ready (cg=0) / previous Bs fully consumed
#pragma unroll
        for (int i = 0; i < 4; i++) {
            int u = t + 256 * i;
            int k = u >> 4, cq = u & 15;
            *(float4*)&Bs[k][cq * 4] = *(const float4*)(preB + k * 256 + cg * 64 + cq * 4);
        }
        __syncthreads();

        float acc[4][4];
#pragma unroll
        for (int i = 0; i < 4; i++)
#pragma unroll
            for (int j = 0; j < 4; j++) acc[i][j] = 0.f;

#pragma unroll 8
        for (int k = 0; k < 64; k++) {
            float4 a  = *(const float4*)&Xs[k][ty * 4];
            float4 b4 = *(const float4*)&Bs[k][tx * 4];
            float ar[4] = {a.x, a.y, a.z, a.w};
            float br[4] = {b4.x, b4.y, b4.z, b4.w};
#pragma unroll
            for (int i = 0; i < 4; i++)
#pragma unroll
                for (int j = 0; j < 4; j++) acc[i][j] = fmaf(ar[i], br[j], acc[i][j]);
        }

        int c0 = cg * 64 + tx * 4;
#pragma unroll
        for (int i = 0; i < 4; i++) {
            int gn = n0 + ty * 4 + i;
            if (gn < NN) {
                float4 o = make_float4(acc[i][0], acc[i][1], acc[i][2], acc[i][3]);
                if (c0 < 128) *(float4*)(g_Hd + (size_t)gn * 128 + c0) = o;
                else          *(float4*)(g_Hs + (size_t)gn * 128 + (c0 - 128)) = o;
            }
        }
    }
}

// ---------------- fused gather+aggregate (2 nodes per block, 8-wide MLP) --------
__global__ __launch_bounds__(256) void k_agg(const float* __restrict__ preb) {
    int n = blockIdx.x * 2 + (threadIdx.x >> 7);
    int f = threadIdx.x & 127;     // 0..127
    int lo = g_rowptr[n], hi = g_rowptr[n + 1];
    float sum = 0.f, sq = 0.f;
    float mn = INFINITY, mx = -INFINITY;
    int p = lo;
    for (; p + 8 <= hi; p += 8) {
        int idx[8];
#pragma unroll
        for (int j = 0; j < 8; j++) idx[j] = g_csrc[p + j];
        float v[8];
#pragma unroll
        for (int j = 0; j < 8; j++) v[j] = g_Hs[(size_t)idx[j] * 128 + f];
#pragma unroll
        for (int j = 0; j < 8; j++) {
            sum += v[j];
            sq   = fmaf(v[j], v[j], sq);
            mn   = fminf(mn, v[j]);
            mx   = fmaxf(mx, v[j]);
        }
    }
    for (; p < hi; p++) {
        float v = g_Hs[(size_t)g_csrc[p] * 128 + f];
        sum += v; sq = fmaf(v, v, sq);
        mn = fminf(mn, v); mx = fmaxf(mx, v);
    }
    float c = g_Hd[(size_t)n * 128 + f] + preb[f];
    int deg = hi - lo;
    float mean, mnO, mxO, sd;
    if (deg > 0) {
        float invc = g_invc[n];
        float ms  = sum * invc;
        float var = sq * invc - ms * ms;
        mean = c + ms; mnO = c + mn; mxO = c + mx;
        sd = sqrtf(fmaxf(var, 0.f) + 1e-5f);
    } else {
        mean = 0.f; mnO = 0.f; mxO = 0.f; sd = sqrtf(1e-5f);
    }
    int tt = f >> 6, ff = f & 63;
    size_t base = (size_t)n * 512 + tt * 256 + ff;
    g_agg[base]       = mean;
    g_agg[base + 64]  = mnO;
    g_agg[base + 128] = mxO;
    g_agg[base + 192] = sd;
}

// ---------------- fused post+lin GEMM (R10-proven) ------------------------------
#define TSTRIDE 4360   // tower stride in floats (4360 % 32 = 8 -> disjoint banks)
__global__ __launch_bounds__(256) void k_postlin(const float* __restrict__ postW,
                                                 const float* __restrict__ postb,
                                                 const float* __restrict__ linW,
                                                 const float* __restrict__ linb,
                                                 float* __restrict__ outp) {
    __shared__ float A13[2 * TSTRIDE]; // [tower][node(64)][k(68 pad)] — 34880 B
    __shared__ float Ws[64][64];       // weights tile — 16384 B
    int t  = threadIdx.x;
    int n0 = blockIdx.x * 64;
    int tx = t & 15, ty = t >> 4;
    int tc = tx >> 3;                  // tower for this thread's columns
    int abase = tc * TSTRIDE + ty * 4 * 68;   // this thread's 4 node rows

    float acc[4][4];
#pragma unroll
    for (int i = 0; i < 4; i++)
#pragma unroll
        for (int j = 0; j < 4; j++) acc[i][j] = 0.f;

    for (int ci = 0; ci < 13; ci++) {
        int kc = ci * 64;
        float4 va[8];
#pragma unroll
        for (int i = 0; i < 8; i++) {
            int u = t + 256 * i;
            int tw = u >> 10, node = (u >> 4) & 63, kq = u & 15;
            int gn = n0 + node;
            float4 v = make_float4(0.f, 0.f, 0.f, 0.f);
            if (gn < NN) {
                if (ci == 0) {
                    v = *(const float4*)(g_hA + (size_t)gn * 64 + kq * 4);
                } else {
                    int k = kc + kq * 4;
                    int j; float s = 1.f;
                    if (ci < 5)      { j = k - 64; }
                    else if (ci < 9) { j = k - 320; s = g_s1[gn]; }
                    else             { j = k - 576; s = g_s2[gn]; }
                    v = *(const float4*)(g_agg + (size_t)gn * 512 + tw * 256 + j);
                    v.x *= s; v.y *= s; v.z *= s; v.w *= s;
                }
            }
            va[i] = v;
        }
        float4 vb[4];
#pragma unroll
        for (int i = 0; i < 4; i++) {
            int u = t + 256 * i;
            int kk = u >> 4, cq = u & 15;
            int tw = cq >> 3, g = (cq * 4) & 31;
            vb[i] = *(const float4*)(postW + tw * 26624 + (kc + kk) * 32 + g);
        }
        __syncthreads();
#pragma unroll
        for (int i = 0; i < 8; i++) {
            int u = t + 256 * i;
            int tw = u >> 10, node = (u >> 4) & 63, kq = u & 15;
            *(float4*)&A13[tw * TSTRIDE + node * 68 + kq * 4] = va[i];
        }
#pragma unroll
        for (int i = 0; i < 4; i++) ((float4*)Ws)[t + 256 * i] = vb[i];
        __syncthreads();

#pragma unroll
        for (int kk = 0; kk < 64; kk += 4) {
            float4 ar4[4];
#pragma unroll
            for (int i = 0; i < 4; i++)
                ar4[i] = *(const float4*)&A13[abase + i * 68 + kk];
#pragma unroll
            for (int d = 0; d < 4; d++) {
                float4 b4 = *(const float4*)&Ws[kk + d][tx * 4];
                float br[4] = {b4.x, b4.y, b4.z, b4.w};
#pragma unroll
                for (int i = 0; i < 4; i++) {
                    float av = (&ar4[i].x)[d];
#pragma unroll
                    for (int j = 0; j < 4; j++) acc[i][j] = fmaf(av, br[j], acc[i][j]);
                }
            }
        }
        __syncthreads();
    }

    // -------- stage 2: P-tile -> smem (tower-0 area), multiply by linW --------
    float4 pbias = *(const float4*)(postb + tx * 4);
#pragma unroll
    for (int i = 0; i < 4; i++) {
        int r = (ty * 4 + i) * 68;
        A13[r + tx * 4 + 0] = acc[i][0] + pbias.x;
        A13[r + tx * 4 + 1] = acc[i][1] + pbias.y;
        A13[r + tx * 4 + 2] = acc[i][2] + pbias.z;
        A13[r + tx * 4 + 3] = acc[i][3] + pbias.w;
    }
#pragma unroll
    for (int i = 0; i < 4; i++)
        ((float4*)Ws)[t + 256 * i] = ((const float4*)linW)[t + 256 * i];
    __syncthreads();

    float acc2[4][4];
#pragma unroll
    for (int i = 0; i < 4; i++)
#pragma unroll
        for (int j = 0; j < 4; j++) acc2[i][j] = 0.f;

    int a2base = ty * 4 * 68;
#pragma unroll
    for (int kk = 0; kk < 64; kk += 4) {
        float4 ar4[4];
#pragma unroll
        for (int i = 0; i < 4; i++)
            ar4[i] = *(const float4*)&A13[a2base + i * 68 + kk];
#pragma unroll
        for (int d = 0; d < 4; d++) {
            float4 b4 = *(const float4*)&Ws[kk + d][tx * 4];
            float br[4] = {b4.x, b4.y, b4.z, b4.w};
#pragma unroll
            for (int i = 0; i < 4; i++) {
                float av = (&ar4[i].x)[d];
#pragma unroll
                for (int j = 0; j < 4; j++) acc2[i][j] = fmaf(av, br[j], acc2[i][j]);
            }
        }
    }

    float* target = outp ? outp : g_hB;
    float4 lbias = *(const float4*)(linb + tx * 4);
    float lsum[4] = {0.f, 0.f, 0.f, 0.f};
    float lsq[4]  = {0.f, 0.f, 0.f, 0.f};
#pragma unroll
    for (int i = 0; i < 4; i++) {
        int gn = n0 + ty * 4 + i;
        if (gn < NN) {
            float o0 = acc2[i][0] + lbias.x, o1 = acc2[i][1] + lbias.y;
            float o2 = acc2[i][2] + lbias.z, o3 = acc2[i][3] + lbias.w;
            *(float4*)(target + (size_t)gn * 64 + tx * 4) = make_float4(o0, o1, o2, o3);
            lsum[0] += o0; lsum[1] += o1; lsum[2] += o2; lsum[3] += o3;
            lsq[0] = fmaf(o0, o0, lsq[0]); lsq[1] = fmaf(o1, o1, lsq[1]);
            lsq[2] = fmaf(o2, o2, lsq[2]); lsq[3] = fmaf(o3, o3, lsq[3]);
        }
    }

    if (!outp) {   // fused BN stats (layer 1)
        __syncthreads();
        float* redS = &A13[TSTRIDE];   // tower-1 area, no longer needed
        float* redQ = &Ws[0][0];
#pragma unroll
        for (int j = 0; j < 4; j++) {
            redS[ty * 68 + tx * 4 + j] = lsum[j];
            redQ[ty * 68 + tx * 4 + j] = lsq[j];
        }
        __syncthreads();
        for (int o = 8; o > 0; o >>= 1) {
            if (ty < o) {
#pragma unroll
                for (int j = 0; j < 4; j++) {
                    redS[ty * 68 + tx * 4 + j] += redS[(ty + o) * 68 + tx * 4 + j];
                    redQ[ty * 68 + tx * 4 + j] += redQ[(ty + o) * 68 + tx * 4 + j];
                }
            }
            __syncthreads();
        }
        if (ty == 0) {
#pragma unroll
            for (int j = 0; j < 4; j++) {
                atomicAdd(&g_bnsum[tx * 4 + j], redS[tx * 4 + j]);
                atomicAdd(&g_bnsq[tx * 4 + j],  redQ[tx * 4 + j]);
            }
        }
    }
}

// ---------------- launch --------------------------------------------------------
extern "C" void kernel_launch(void* const* d_in, const int* in_sizes, int n_in,
                              void* d_out, int out_size) {
    const float* x       = (const float*)d_in[0];
    const float* embed_W = (const float*)d_in[1];
    const float* embed_b = (const float*)d_in[2];
    const float* pre_W1  = (const float*)d_in[3];
    const float* pre_b1  = (const float*)d_in[4];
    const float* post_W1 = (const float*)d_in[5];
    const float* post_b1 = (const float*)d_in[6];
    const float* lin_W1  = (const float*)d_in[7];
    const float* lin_b1  = (const float*)d_in[8];
    const float* bn_g    = (const float*)d_in[9];
    const float* bn_b    = (const float*)d_in[10];
    const float* pre_W2  = (const float*)d_in[11];
    const float* pre_b2  = (const float*)d_in[12];
    const float* post_W2 = (const float*)d_in[13];
    const float* post_b2 = (const float*)d_in[14];
    const float* lin_W2  = (const float*)d_in[15];
    const float* lin_b2  = (const float*)d_in[16];
    const int*   src     = (const int*)d_in[17];
    const int*   dst     = (const int*)d_in[18];
    float* out = (float*)d_out;

    const int GN256 = (NN + 255) / 256;
    const int GE256 = NE / 256;
    const int GT64  = (NN + 63) / 64;      // 782

    // graph structure (shared by both layers)
    k_init<<<GN256, 256>>>();
    k_degree<<<GE256, 256>>>(dst);
    k_graph<<<1, 1024>>>();                // logmean + scan + scales + cursors
    k_scatter<<<GE256, 256>>>(src, dst);

    // embed + weight packing
    k_embed<<<GT64, 256>>>(x, embed_W, embed_b);
    k_preB2both<<<128, 256>>>(pre_W1, pre_W2);

    // ---- layer 1 ----
    k_hds<<<GT64, 256>>>(0, nullptr, nullptr);
    k_agg<<<NN / 2, 256>>>(pre_b1);
    k_postlin<<<GT64, 256>>>(post_W1, post_b1, lin_W1, lin_b1, nullptr); // + BN stats

    // ---- layer 2 (k_hds computes BN scale/shift inline + applies BN+ReLU) ----
    k_hds<<<GT64, 256>>>(1, bn_g, bn_b);
    k_agg<<<NN / 2, 256>>>(pre_b2);
    k_postlin<<<GT64, 256>>>(post_W2, post_b2, lin_W2, lin_b2, out);
}

// round 12
// speedup vs baseline: 1.1097x; 1.1097x over previous
#include <cuda_runtime.h>
#include <math.h>

#define NN 50000
#define NE 800000
#define IND 128

// ---------------- scratch ------------------------------------------------------
__device__ float g_hA[NN * 64];        // layer input (embed out / post-BN)
__device__ float g_hB[NN * 64];        // layer1 output (pre-BN)
__device__ float g_Hd[NN * 128];       // h @ preW_top  (dst half)
__device__ float g_Hs[NN * 128];       // h @ preW_bot  (src half) — 25.6MB, L2-resident
__device__ float g_agg[NN * 512];      // per node: [t][stat(mean,min,max,std)][f]
__device__ int   g_deg[NN];
__device__ float g_invc[NN];
__device__ float g_s1[NN];
__device__ float g_s2[NN];
__device__ int   g_rowptr[NN + 1];
__device__ int   g_cursor[NN];
__device__ int   g_csrc[NE];
__device__ float g_preB2a[64 * 256];   // layer1 packed preW  [k][c]
__device__ float g_preB2b[64 * 256];   // layer2 packed preW  [k][c]
__device__ float g_sumlog;
__device__ float g_bnsum[64];
__device__ float g_bnsq[64];

// ---------------- setup --------------------------------------------------------
__global__ void k_init() {
    int i = blockIdx.x * blockDim.x + threadIdx.x;
    if (i < NN) { g_deg[i] = 0; g_cursor[i] = 0; }
    if (i == 0) g_sumlog = 0.f;
    if (i < 64) { g_bnsum[i] = 0.f; g_bnsq[i] = 0.f; }
}

__global__ void k_degree(const int* __restrict__ dst) {
    int e = blockIdx.x * blockDim.x + threadIdx.x;
    if (e < NE) atomicAdd(&g_deg[dst[e]], 1);
}

__global__ void k_logsum() {
    __shared__ float s[256];
    int i = blockIdx.x * 256 + threadIdx.x;
    float v = 0.f;
    if (i < NN) v = logf((float)g_deg[i] + 1.f);
    s[threadIdx.x] = v; __syncthreads();
    for (int o = 128; o > 0; o >>= 1) {
        if (threadIdx.x < o) s[threadIdx.x] += s[threadIdx.x + o];
        __syncthreads();
    }
    if (threadIdx.x == 0) atomicAdd(&g_sumlog, s[0]);
}

__global__ void k_scales() {
    int i = blockIdx.x * blockDim.x + threadIdx.x;
    if (i >= NN) return;
    float avg = g_sumlog / (float)NN;
    float dc  = fmaxf((float)g_deg[i], 1.f);
    g_invc[i] = 1.f / dc;
    float ld  = logf(dc + 1.f);
    g_s1[i] = ld / avg;
    g_s2[i] = avg / ld;
}

__global__ void k_scan() {
    __shared__ int ssum[1024];
    const int CH = (NN + 1023) / 1024;
    int t  = threadIdx.x;
    int lo = t * CH, hi = min(lo + CH, NN);
    int s = 0;
    for (int i = lo; i < hi; i++) s += g_deg[i];
    ssum[t] = s; __syncthreads();
    for (int o = 1; o < 1024; o <<= 1) {
        int v = (t >= o) ? ssum[t - o] : 0;
        __syncthreads();
        ssum[t] += v;
        __syncthreads();
    }
    int run = (t == 0) ? 0 : ssum[t - 1];
    for (int i = lo; i < hi; i++) { g_rowptr[i] = run; run += g_deg[i]; }
    if (t == 1023) g_rowptr[NN] = ssum[1023];
}

__global__ void k_scatter(const int* __restrict__ src, const int* __restrict__ dst) {
    int e = blockIdx.x * blockDim.x + threadIdx.x;
    if (e >= NE) return;
    int d = dst[e];
    int pos = g_rowptr[d] + atomicAdd(&g_cursor[d], 1);
    g_csrc[pos] = src[e];
}

// pack both layers' preW (T,128,64) into [64][256]: col c: half=c>>7, j=c&127
__global__ void k_preB2both(const float* __restrict__ preW1,
                            const float* __restrict__ preW2) {
    int i = blockIdx.x * blockDim.x + threadIdx.x;
    if (i >= 2 * 64 * 256) return;
    int which = i >> 14;               // 0: layer1, 1: layer2
    int u = i & 16383;
    int k = u >> 8, c = u & 255;
    int half = c >> 7, j = c & 127;
    int t = j >> 6, f = j & 63;
    const float* w = which ? preW2 : preW1;
    float* o = which ? g_preB2b : g_preB2a;
    o[u] = w[t * 8192 + (half * 64 + k) * 64 + f];
}

// ---------------- embed GEMM: h = x @ W + b  (K=128, N=64) ----------------------
__global__ __launch_bounds__(256) void k_embed(const float* __restrict__ x,
                                               const float* __restrict__ W,
                                               const float* __restrict__ b) {
    __shared__ float Xs[128][64];
    __shared__ float Ws[128][64];
    int t  = threadIdx.x;
    int n0 = blockIdx.x * 64;

    for (int i = t; i < 2048; i += 256)
        ((float4*)Ws)[i] = ((const float4*)W)[i];

    int row = t & 63, kq = t >> 6;
    int gr = n0 + row;
#pragma unroll
    for (int j = 0; j < 8; j++) {
        int k = kq * 32 + j * 4;
        float4 v = make_float4(0.f, 0.f, 0.f, 0.f);
        if (gr < NN) v = *(const float4*)(x + (size_t)gr * IND + k);
        Xs[k][row] = v.x; Xs[k + 1][row] = v.y; Xs[k + 2][row] = v.z; Xs[k + 3][row] = v.w;
    }
    __syncthreads();

    int tx = t & 15, ty = t >> 4;
    float acc[4][4];
#pragma unroll
    for (int i = 0; i < 4; i++)
#pragma unroll
        for (int j = 0; j < 4; j++) acc[i][j] = 0.f;

#pragma unroll 8
    for (int k = 0; k < 128; k++) {
        float4 a  = *(const float4*)&Xs[k][ty * 4];
        float4 b4 = *(const float4*)&Ws[k][tx * 4];
        float ar[4] = {a.x, a.y, a.z, a.w};
        float br[4] = {b4.x, b4.y, b4.z, b4.w};
#pragma unroll
        for (int i = 0; i < 4; i++)
#pragma unroll
            for (int j = 0; j < 4; j++) acc[i][j] = fmaf(ar[i], br[j], acc[i][j]);
    }

    float4 bias = *(const float4*)(b + tx * 4);
#pragma unroll
    for (int i = 0; i < 4; i++) {
        int gn = n0 + ty * 4 + i;
        if (gn < NN) {
            float4 o = make_float4(acc[i][0] + bias.x, acc[i][1] + bias.y,
                                   acc[i][2] + bias.z, acc[i][3] + bias.w);
            *(float4*)(g_hA + (size_t)gn * 64 + tx * 4) = o;
        }
    }
}

// ---------------- Hd/Hs GEMM: [Hd|Hs] = h @ preB2  (K=64, N=256) ----------------
// layer==1: recomputes BN scale/shift in smem from g_bnsum/g_bnsq (replaces the
// k_bnfin launch) and applies BN+ReLU to g_hB during the Xs load, writing g_hA.
__global__ __launch_bounds__(256) void k_hds(int layer,
                                             const float* __restrict__ gamma,
                                             const float* __restrict__ beta) {
    __shared__ float Xs[64][64];   // [k][node]
    __shared__ float Bs[64][64];   // [k][c]
    __shared__ float bsc[64], bsh[64];
    int t  = threadIdx.x;
    int n0 = blockIdx.x * 64;
    const float* preB = layer ? g_preB2b : g_preB2a;

    if (layer == 1) {
        if (t < 64) {
            float mu  = g_bnsum[t] / (float)NN;
            float var = g_bnsq[t] / (float)NN - mu * mu;
            float sc  = gamma[t] * rsqrtf(var + 1e-5f);
            bsc[t] = sc;
            bsh[t] = beta[t] - mu * sc;
        }
        __syncthreads();
    }

    int node = t & 63, kq = t >> 6;
    int gr = n0 + node;
#pragma unroll
    for (int j = 0; j < 4; j++) {
        int k = kq * 16 + j * 4;
        float4 v = make_float4(0.f, 0.f, 0.f, 0.f);
        if (gr < NN) {
            if (layer == 0) {
                v = *(const float4*)(g_hA + (size_t)gr * 64 + k);
            } else {
                float4 hv = *(const float4*)(g_hB + (size_t)gr * 64 + k);
                v.x = fmaxf(hv.x * bsc[k]     + bsh[k],     0.f);
                v.y = fmaxf(hv.y * bsc[k + 1] + bsh[k + 1], 0.f);
                v.z = fmaxf(hv.z * bsc[k + 2] + bsh[k + 2], 0.f);
                v.w = fmaxf(hv.w * bsc[k + 3] + bsh[k + 3], 0.f);
                *(float4*)(g_hA + (size_t)gr * 64 + k) = v;   // layer-2 h input
            }
        }
        Xs[k][node] = v.x; Xs[k + 1][node] = v.y; Xs[k + 2][node] = v.z; Xs[k + 3][node] = v.w;
    }

    int tx = t & 15, ty = t >> 4;

    for (int cg = 0; cg < 4; cg++) {
        __syncthreads();   // Xs ready (cg=0) / previous Bs fully consumed
#pragma unroll
        for (int i = 0; i < 4; i++) {
            int u = t + 256 * i;
            int k = u >> 4, cq = u & 15;
            *(float4*)&Bs[k][cq * 4] = *(const float4*)(preB + k * 256 + cg * 64 + cq * 4);
        }
        __syncthreads();

        float acc[4][4];
#pragma unroll
        for (int i = 0; i < 4; i++)
#pragma unroll
            for (int j = 0; j < 4; j++) acc[i][j] = 0.f;

#pragma unroll 8
        for (int k = 0; k < 64; k++) {
            float4 a  = *(const float4*)&Xs[k][ty * 4];
            float4 b4 = *(const float4*)&Bs[k][tx * 4];
            float ar[4] = {a.x, a.y, a.z, a.w};
            float br[4] = {b4.x, b4.y, b4.z, b4.w};
#pragma unroll
            for (int i = 0; i < 4; i++)
#pragma unroll
                for (int j = 0; j < 4; j++) acc[i][j] = fmaf(ar[i], br[j], acc[i][j]);
        }

        int c0 = cg * 64 + tx * 4;
#pragma unroll
        for (int i = 0; i < 4; i++) {
            int gn = n0 + ty * 4 + i;
            if (gn < NN) {
                float4 o = make_float4(acc[i][0], acc[i][1], acc[i][2], acc[i][3]);
                if (c0 < 128) *(float4*)(g_Hd + (size_t)gn * 128 + c0) = o;
                else          *(float4*)(g_Hs + (size_t)gn * 128 + (c0 - 128)) = o;
            }
        }
    }
}

// ---------------- fused gather+aggregate (2 nodes per block, 4-wide proven) -----
__global__ __launch_bounds__(256) void k_agg(const float* __restrict__ preb) {
    int n = blockIdx.x * 2 + (threadIdx.x >> 7);
    int f = threadIdx.x & 127;     // 0..127
    int lo = g_rowptr[n], hi = g_rowptr[n + 1];
    float sum = 0.f, sq = 0.f;
    float mn = INFINITY, mx = -INFINITY;
    int p = lo;
    for (; p + 4 <= hi; p += 4) {
        int i0 = g_csrc[p], i1 = g_csrc[p + 1], i2 = g_csrc[p + 2], i3 = g_csrc[p + 3];
        float v0 = g_Hs[(size_t)i0 * 128 + f];
        float v1 = g_Hs[(size_t)i1 * 128 + f];
        float v2 = g_Hs[(size_t)i2 * 128 + f];
        float v3 = g_Hs[(size_t)i3 * 128 + f];
        sum += (v0 + v1) + (v2 + v3);
        sq  = fmaf(v0, v0, fmaf(v1, v1, fmaf(v2, v2, fmaf(v3, v3, sq))));
        mn = fminf(mn, fminf(fminf(v0, v1), fminf(v2, v3)));
        mx = fmaxf(mx, fmaxf(fmaxf(v0, v1), fmaxf(v2, v3)));
    }
    for (; p < hi; p++) {
        float v = g_Hs[(size_t)g_csrc[p] * 128 + f];
        sum += v; sq = fmaf(v, v, sq);
        mn = fminf(mn, v); mx = fmaxf(mx, v);
    }
    float c = g_Hd[(size_t)n * 128 + f] + preb[f];
    int deg = hi - lo;
    float mean, mnO, mxO, sd;
    if (deg > 0) {
        float invc = g_invc[n];
        float ms  = sum * invc;
        float var = sq * invc - ms * ms;
        mean = c + ms; mnO = c + mn; mxO = c + mx;
        sd = sqrtf(fmaxf(var, 0.f) + 1e-5f);
    } else {
        mean = 0.f; mnO = 0.f; mxO = 0.f; sd = sqrtf(1e-5f);
    }
    int tt = f >> 6, ff = f & 63;
    size_t base = (size_t)n * 512 + tt * 256 + ff;
    g_agg[base]       = mean;
    g_agg[base + 64]  = mnO;
    g_agg[base + 128] = mxO;
    g_agg[base + 192] = sd;
}

// ---------------- fused post+lin GEMM (R10-proven) ------------------------------
#define TSTRIDE 4360   // tower stride in floats (4360 % 32 = 8 -> disjoint banks)
__global__ __launch_bounds__(256) void k_postlin(const float* __restrict__ postW,
                                                 const float* __restrict__ postb,
                                                 const float* __restrict__ linW,
                                                 const float* __restrict__ linb,
                                                 float* __restrict__ outp) {
    __shared__ float A13[2 * TSTRIDE]; // [tower][node(64)][k(68 pad)] — 34880 B
    __shared__ float Ws[64][64];       // weights tile — 16384 B
    int t  = threadIdx.x;
    int n0 = blockIdx.x * 64;
    int tx = t & 15, ty = t >> 4;
    int tc = tx >> 3;                  // tower for this thread's columns
    int abase = tc * TSTRIDE + ty * 4 * 68;   // this thread's 4 node rows

    float acc[4][4];
#pragma unroll
    for (int i = 0; i < 4; i++)
#pragma unroll
        for (int j = 0; j < 4; j++) acc[i][j] = 0.f;

    for (int ci = 0; ci < 13; ci++) {
        int kc = ci * 64;
        float4 va[8];
#pragma unroll
        for (int i = 0; i < 8; i++) {
            int u = t + 256 * i;
            int tw = u >> 10, node = (u >> 4) & 63, kq = u & 15;
            int gn = n0 + node;
            float4 v = make_float4(0.f, 0.f, 0.f, 0.f);
            if (gn < NN) {
                if (ci == 0) {
                    v = *(const float4*)(g_hA + (size_t)gn * 64 + kq * 4);
                } else {
                    int k = kc + kq * 4;
                    int j; float s = 1.f;
                    if (ci < 5)      { j = k - 64; }
                    else if (ci < 9) { j = k - 320; s = g_s1[gn]; }
                    else             { j = k - 576; s = g_s2[gn]; }
                    v = *(const float4*)(g_agg + (size_t)gn * 512 + tw * 256 + j);
                    v.x *= s; v.y *= s; v.z *= s; v.w *= s;
                }
            }
            va[i] = v;
        }
        float4 vb[4];
#pragma unroll
        for (int i = 0; i < 4; i++) {
            int u = t + 256 * i;
            int kk = u >> 4, cq = u & 15;
            int tw = cq >> 3, g = (cq * 4) & 31;
            vb[i] = *(const float4*)(postW + tw * 26624 + (kc + kk) * 32 + g);
        }
        __syncthreads();
#pragma unroll
        for (int i = 0; i < 8; i++) {
            int u = t + 256 * i;
            int tw = u >> 10, node = (u >> 4) & 63, kq = u & 15;
            *(float4*)&A13[tw * TSTRIDE + node * 68 + kq * 4] = va[i];
        }
#pragma unroll
        for (int i = 0; i < 4; i++) ((float4*)Ws)[t + 256 * i] = vb[i];
        __syncthreads();

#pragma unroll
        for (int kk = 0; kk < 64; kk += 4) {
            float4 ar4[4];
#pragma unroll
            for (int i = 0; i < 4; i++)
                ar4[i] = *(const float4*)&A13[abase + i * 68 + kk];
#pragma unroll
            for (int d = 0; d < 4; d++) {
                float4 b4 = *(const float4*)&Ws[kk + d][tx * 4];
                float br[4] = {b4.x, b4.y, b4.z, b4.w};
#pragma unroll
                for (int i = 0; i < 4; i++) {
                    float av = (&ar4[i].x)[d];
#pragma unroll
                    for (int j = 0; j < 4; j++) acc[i][j] = fmaf(av, br[j], acc[i][j]);
                }
            }
        }
        __syncthreads();
    }

    // -------- stage 2: P-tile -> smem (tower-0 area), multiply by linW --------
    float4 pbias = *(const float4*)(postb + tx * 4);
#pragma unroll
    for (int i = 0; i < 4; i++) {
        int r = (ty * 4 + i) * 68;
        A13[r + tx * 4 + 0] = acc[i][0] + pbias.x;
        A13[r + tx * 4 + 1] = acc[i][1] + pbias.y;
        A13[r + tx * 4 + 2] = acc[i][2] + pbias.z;
        A13[r + tx * 4 + 3] = acc[i][3] + pbias.w;
    }
#pragma unroll
    for (int i = 0; i < 4; i++)
        ((float4*)Ws)[t + 256 * i] = ((const float4*)linW)[t + 256 * i];
    __syncthreads();

    float acc2[4][4];
#pragma unroll
    for (int i = 0; i < 4; i++)
#pragma unroll
        for (int j = 0; j < 4; j++) acc2[i][j] = 0.f;

    int a2base = ty * 4 * 68;
#pragma unroll
    for (int kk = 0; kk < 64; kk += 4) {
        float4 ar4[4];
#pragma unroll
        for (int i = 0; i < 4; i++)
            ar4[i] = *(const float4*)&A13[a2base + i * 68 + kk];
#pragma unroll
        for (int d = 0; d < 4; d++) {
            float4 b4 = *(const float4*)&Ws[kk + d][tx * 4];
            float br[4] = {b4.x, b4.y, b4.z, b4.w};
#pragma unroll
            for (int i = 0; i < 4; i++) {
                float av = (&ar4[i].x)[d];
#pragma unroll
                for (int j = 0; j < 4; j++) acc2[i][j] = fmaf(av, br[j], acc2[i][j]);
            }
        }
    }

    float* target = outp ? outp : g_hB;
    float4 lbias = *(const float4*)(linb + tx * 4);
    float lsum[4] = {0.f, 0.f, 0.f, 0.f};
    float lsq[4]  = {0.f, 0.f, 0.f, 0.f};
#pragma unroll
    for (int i = 0; i < 4; i++) {
        int gn = n0 + ty * 4 + i;
        if (gn < NN) {
            float o0 = acc2[i][0] + lbias.x, o1 = acc2[i][1] + lbias.y;
            float o2 = acc2[i][2] + lbias.z, o3 = acc2[i][3] + lbias.w;
            *(float4*)(target + (size_t)gn * 64 + tx * 4) = make_float4(o0, o1, o2, o3);
            lsum[0] += o0; lsum[1] += o1; lsum[2] += o2; lsum[3] += o3;
            lsq[0] = fmaf(o0, o0, lsq[0]); lsq[1] = fmaf(o1, o1, lsq[1]);
            lsq[2] = fmaf(o2, o2, lsq[2]); lsq[3] = fmaf(o3, o3, lsq[3]);
        }
    }

    if (!outp) {   // fused BN stats (layer 1)
        __syncthreads();
        float* redS = &A13[TSTRIDE];   // tower-1 area, no longer needed
        float* redQ = &Ws[0][0];
#pragma unroll
        for (int j = 0; j < 4; j++) {
            redS[ty * 68 + tx * 4 + j] = lsum[j];
            redQ[ty * 68 + tx * 4 + j] = lsq[j];
        }
        __syncthreads();
        for (int o = 8; o > 0; o >>= 1) {
            if (ty < o) {
#pragma unroll
                for (int j = 0; j < 4; j++) {
                    redS[ty * 68 + tx * 4 + j] += redS[(ty + o) * 68 + tx * 4 + j];
                    redQ[ty * 68 + tx * 4 + j] += redQ[(ty + o) * 68 + tx * 4 + j];
                }
            }
            __syncthreads();
        }
        if (ty == 0) {
#pragma unroll
            for (int j = 0; j < 4; j++) {
                atomicAdd(&g_bnsum[tx * 4 + j], redS[tx * 4 + j]);
                atomicAdd(&g_bnsq[tx * 4 + j],  redQ[tx * 4 + j]);
            }
        }
    }
}

// ---------------- launch --------------------------------------------------------
extern "C" void kernel_launch(void* const* d_in, const int* in_sizes, int n_in,
                              void* d_out, int out_size) {
    const float* x       = (const float*)d_in[0];
    const float* embed_W = (const float*)d_in[1];
    const float* embed_b = (const float*)d_in[2];
    const float* pre_W1  = (const float*)d_in[3];
    const float* pre_b1  = (const float*)d_in[4];
    const float* post_W1 = (const float*)d_in[5];
    const float* post_b1 = (const float*)d_in[6];
    const float* lin_W1  = (const float*)d_in[7];
    const float* lin_b1  = (const float*)d_in[8];
    const float* bn_g    = (const float*)d_in[9];
    const float* bn_b    = (const float*)d_in[10];
    const float* pre_W2  = (const float*)d_in[11];
    const float* pre_b2  = (const float*)d_in[12];
    const float* post_W2 = (const float*)d_in[13];
    const float* post_b2 = (const float*)d_in[14];
    const float* lin_W2  = (const float*)d_in[15];
    const float* lin_b2  = (const float*)d_in[16];
    const int*   src     = (const int*)d_in[17];
    const int*   dst     = (const int*)d_in[18];
    float* out = (float*)d_out;

    const int GN256 = (NN + 255) / 256;
    const int GE256 = NE / 256;
    const int GT64  = (NN + 63) / 64;      // 782

    // graph structure (shared by both layers)
    k_init<<<GN256, 256>>>();
    k_degree<<<GE256, 256>>>(dst);
    k_logsum<<<GN256, 256>>>();
    k_scales<<<GN256, 256>>>();
    k_scan<<<1, 1024>>>();
    k_scatter<<<GE256, 256>>>(src, dst);

    // embed + weight packing
    k_embed<<<GT64, 256>>>(x, embed_W, embed_b);
    k_preB2both<<<128, 256>>>(pre_W1, pre_W2);

    // ---- layer 1 ----
    k_hds<<<GT64, 256>>>(0, nullptr, nullptr);
    k_agg<<<NN / 2, 256>>>(pre_b1);
    k_postlin<<<GT64, 256>>>(post_W1, post_b1, lin_W1, lin_b1, nullptr); // + BN stats

    // ---- layer 2 (k_hds computes BN scale/shift inline + applies BN+ReLU) ----
    k_hds<<<GT64, 256>>>(1, bn_g, bn_b);
    k_agg<<<NN / 2, 256>>>(pre_b2);
    k_postlin<<<GT64, 256>>>(post_W2, post_b2, lin_W2, lin_b2, out);
}

// round 13
// speedup vs baseline: 1.1121x; 1.0022x over previous
#include <cuda_runtime.h>
#include <math.h>

#define NN 50000
#define NE 800000
#define IND 128

// ---------------- scratch ------------------------------------------------------
__device__ float g_hA[NN * 64];        // layer input (embed out / post-BN)
__device__ float g_hB[NN * 64];        // layer1 output (pre-BN)
__device__ float g_Hd[NN * 128];       // h @ preW_top  (dst half)
__device__ float g_Hs[NN * 128];       // h @ preW_bot  (src half) — 25.6MB, L2-resident
__device__ float g_agg[NN * 512];      // per node: [t][stat(mean,min,max,std)][f]
__device__ int   g_deg[NN];
__device__ float g_s1[NN];
__device__ float g_s2[NN];
__device__ int   g_rowptr[NN + 1];
__device__ int   g_cursor[NN];
__device__ int   g_csrc[NE];
__device__ float g_preB2a[64 * 256];   // layer1 packed preW  [k][c]
__device__ float g_preB2b[64 * 256];   // layer2 packed preW  [k][c]
__device__ float g_sumlog;
__device__ float g_bnsum[64];
__device__ float g_bnsq[64];

// ---------------- setup --------------------------------------------------------
__global__ void k_init() {
    int i = blockIdx.x * blockDim.x + threadIdx.x;
    if (i < NN) { g_deg[i] = 0; g_cursor[i] = 0; }
    if (i == 0) g_sumlog = 0.f;
    if (i < 64) { g_bnsum[i] = 0.f; g_bnsq[i] = 0.f; }
}

__global__ void k_degree(const int* __restrict__ dst) {
    int e = blockIdx.x * blockDim.x + threadIdx.x;
    if (e < NE) atomicAdd(&g_deg[dst[e]], 1);
}

__global__ void k_logsum() {
    __shared__ float s[256];
    int i = blockIdx.x * 256 + threadIdx.x;
    float v = 0.f;
    if (i < NN) v = logf((float)g_deg[i] + 1.f);
    s[threadIdx.x] = v; __syncthreads();
    for (int o = 128; o > 0; o >>= 1) {
        if (threadIdx.x < o) s[threadIdx.x] += s[threadIdx.x + o];
        __syncthreads();
    }
    if (threadIdx.x == 0) atomicAdd(&g_sumlog, s[0]);
}

__global__ void k_scan() {
    __shared__ int ssum[1024];
    const int CH = (NN + 1023) / 1024;
    int t  = threadIdx.x;
    int lo = t * CH, hi = min(lo + CH, NN);
    int s = 0;
    for (int i = lo; i < hi; i++) s += g_deg[i];
    ssum[t] = s; __syncthreads();
    for (int o = 1; o < 1024; o <<= 1) {
        int v = (t >= o) ? ssum[t - o] : 0;
        __syncthreads();
        ssum[t] += v;
        __syncthreads();
    }
    int run = (t == 0) ? 0 : ssum[t - 1];
    for (int i = lo; i < hi; i++) { g_rowptr[i] = run; run += g_deg[i]; }
    if (t == 1023) g_rowptr[NN] = ssum[1023];
}

__global__ void k_scatter(const int* __restrict__ src, const int* __restrict__ dst) {
    int e = blockIdx.x * blockDim.x + threadIdx.x;
    if (e >= NE) return;
    int d = dst[e];
    int pos = g_rowptr[d] + atomicAdd(&g_cursor[d], 1);
    g_csrc[pos] = src[e];
}

// pack both layers' preW (T,128,64) into [64][256]: col c: half=c>>7, j=c&127
__global__ void k_preB2both(const float* __restrict__ preW1,
                            const float* __restrict__ preW2) {
    int i = blockIdx.x * blockDim.x + threadIdx.x;
    if (i >= 2 * 64 * 256) return;
    int which = i >> 14;               // 0: layer1, 1: layer2
    int u = i & 16383;
    int k = u >> 8, c = u & 255;
    int half = c >> 7, j = c & 127;
    int t = j >> 6, f = j & 63;
    const float* w = which ? preW2 : preW1;
    float* o = which ? g_preB2b : g_preB2a;
    o[u] = w[t * 8192 + (half * 64 + k) * 64 + f];
}

// ---------------- fused embed + layer-1 Hd/Hs -----------------------------------
// Stage A: h = x @ embed_W + b (K=128, N=64)  -> g_hA and smem (transposed)
// Stage B: [Hd|Hs] = h @ preB2a (K=64, N=256) -> g_Hd/g_Hs (proven hds loop)
__global__ __launch_bounds__(256) void k_embedhds(const float* __restrict__ x,
                                                  const float* __restrict__ W,
                                                  const float* __restrict__ b) {
    __shared__ float Xs[128][64];      // stage A: x-tile [k][row]; stage B rows 0-63: h [k][node]
    __shared__ float Ws[128][64];      // stage A: embed_W [k][col]; stage B rows 0-63: preB chunk
    int t  = threadIdx.x;
    int n0 = blockIdx.x * 64;

    for (int i = t; i < 2048; i += 256)
        ((float4*)Ws)[i] = ((const float4*)W)[i];

    int row = t & 63, kq = t >> 6;
    int gr = n0 + row;
#pragma unroll
    for (int j = 0; j < 8; j++) {
        int k = kq * 32 + j * 4;
        float4 v = make_float4(0.f, 0.f, 0.f, 0.f);
        if (gr < NN) v = *(const float4*)(x + (size_t)gr * IND + k);
        Xs[k][row] = v.x; Xs[k + 1][row] = v.y; Xs[k + 2][row] = v.z; Xs[k + 3][row] = v.w;
    }
    __syncthreads();

    int tx = t & 15, ty = t >> 4;
    float acc[4][4];
#pragma unroll
    for (int i = 0; i < 4; i++)
#pragma unroll
        for (int j = 0; j < 4; j++) acc[i][j] = 0.f;

#pragma unroll 8
    for (int k = 0; k < 128; k++) {
        float4 a  = *(const float4*)&Xs[k][ty * 4];
        float4 b4 = *(const float4*)&Ws[k][tx * 4];
        float ar[4] = {a.x, a.y, a.z, a.w};
        float br[4] = {b4.x, b4.y, b4.z, b4.w};
#pragma unroll
        for (int i = 0; i < 4; i++)
#pragma unroll
            for (int j = 0; j < 4; j++) acc[i][j] = fmaf(ar[i], br[j], acc[i][j]);
    }

    float4 bias = *(const float4*)(b + tx * 4);
    __syncthreads();   // all embed reads of Xs done before overwrite
#pragma unroll
    for (int i = 0; i < 4; i++) {
        int gn = n0 + ty * 4 + i;
        float o0 = acc[i][0] + bias.x, o1 = acc[i][1] + bias.y;
        float o2 = acc[i][2] + bias.z, o3 = acc[i][3] + bias.w;
        if (gn < NN)
            *(float4*)(g_hA + (size_t)gn * 64 + tx * 4) = make_float4(o0, o1, o2, o3);
        // transposed store: h[k][node]
        int node = ty * 4 + i;
        Xs[tx * 4 + 0][node] = o0;
        Xs[tx * 4 + 1][node] = o1;
        Xs[tx * 4 + 2][node] = o2;
        Xs[tx * 4 + 3][node] = o3;
    }

    // ---- stage B: proven hds column-group loop (h in Xs rows 0-63) ----
    float (*Bs)[64] = (float(*)[64])Ws;
    for (int cg = 0; cg < 4; cg++) {
        __syncthreads();   // h ready (cg=0) / previous Bs fully consumed
#pragma unroll
        for (int i = 0; i < 4; i++) {
            int u = t + 256 * i;
            int k = u >> 4, cq = u & 15;
            *(float4*)&Bs[k][cq * 4] = *(const float4*)(g_preB2a + k * 256 + cg * 64 + cq * 4);
        }
        __syncthreads();

        float acc2[4][4];
#pragma unroll
        for (int i = 0; i < 4; i++)
#pragma unroll
            for (int j = 0; j < 4; j++) acc2[i][j] = 0.f;

#pragma unroll 8
        for (int k = 0; k < 64; k++) {
            float4 a  = *(const float4*)&Xs[k][ty * 4];
            float4 b4 = *(const float4*)&Bs[k][tx * 4];
            float ar[4] = {a.x, a.y, a.z, a.w};
            float br[4] = {b4.x, b4.y, b4.z, b4.w};
#pragma unroll
            for (int i = 0; i < 4; i++)
#pragma unroll
                for (int j = 0; j < 4; j++) acc2[i][j] = fmaf(ar[i], br[j], acc2[i][j]);
        }

        int c0 = cg * 64 + tx * 4;
#pragma unroll
        for (int i = 0; i < 4; i++) {
            int gn = n0 + ty * 4 + i;
            if (gn < NN) {
                float4 o = make_float4(acc2[i][0], acc2[i][1], acc2[i][2], acc2[i][3]);
                if (c0 < 128) *(float4*)(g_Hd + (size_t)gn * 128 + c0) = o;
                else          *(float4*)(g_Hs + (size_t)gn * 128 + (c0 - 128)) = o;
            }
        }
    }
}

// ---------------- layer-2 Hd/Hs GEMM with inline BN+ReLU ------------------------
__global__ __launch_bounds__(256) void k_hds1(const float* __restrict__ gamma,
                                              const float* __restrict__ beta) {
    __shared__ float Xs[64][64];   // [k][node]
    __shared__ float Bs[64][64];   // [k][c]
    __shared__ float bsc[64], bsh[64];
    int t  = threadIdx.x;
    int n0 = blockIdx.x * 64;

    if (t < 64) {
        float mu  = g_bnsum[t] / (float)NN;
        float var = g_bnsq[t] / (float)NN - mu * mu;
        float sc  = gamma[t] * rsqrtf(var + 1e-5f);
        bsc[t] = sc;
        bsh[t] = beta[t] - mu * sc;
    }
    __syncthreads();

    int node = t & 63, kq = t >> 6;
    int gr = n0 + node;
#pragma unroll
    for (int j = 0; j < 4; j++) {
        int k = kq * 16 + j * 4;
        float4 v = make_float4(0.f, 0.f, 0.f, 0.f);
        if (gr < NN) {
            float4 hv = *(const float4*)(g_hB + (size_t)gr * 64 + k);
            v.x = fmaxf(hv.x * bsc[k]     + bsh[k],     0.f);
            v.y = fmaxf(hv.y * bsc[k + 1] + bsh[k + 1], 0.f);
            v.z = fmaxf(hv.z * bsc[k + 2] + bsh[k + 2], 0.f);
            v.w = fmaxf(hv.w * bsc[k + 3] + bsh[k + 3], 0.f);
            *(float4*)(g_hA + (size_t)gr * 64 + k) = v;   // layer-2 h input
        }
        Xs[k][node] = v.x; Xs[k + 1][node] = v.y; Xs[k + 2][node] = v.z; Xs[k + 3][node] = v.w;
    }

    int tx = t & 15, ty = t >> 4;

    for (int cg = 0; cg < 4; cg++) {
        __syncthreads();
#pragma unroll
        for (int i = 0; i < 4; i++) {
            int u = t + 256 * i;
            int k = u >> 4, cq = u & 15;
            *(float4*)&Bs[k][cq * 4] = *(const float4*)(g_preB2b + k * 256 + cg * 64 + cq * 4);
        }
        __syncthreads();

        float acc[4][4];
#pragma unroll
        for (int i = 0; i < 4; i++)
#pragma unroll
            for (int j = 0; j < 4; j++) acc[i][j] = 0.f;

#pragma unroll 8
        for (int k = 0; k < 64; k++) {
            float4 a  = *(const float4*)&Xs[k][ty * 4];
            float4 b4 = *(const float4*)&Bs[k][tx * 4];
            float ar[4] = {a.x, a.y, a.z, a.w};
            float br[4] = {b4.x, b4.y, b4.z, b4.w};
#pragma unroll
            for (int i = 0; i < 4; i++)
#pragma unroll
                for (int j = 0; j < 4; j++) acc[i][j] = fmaf(ar[i], br[j], acc[i][j]);
        }

        int c0 = cg * 64 + tx * 4;
#pragma unroll
        for (int i = 0; i < 4; i++) {
            int gn = n0 + ty * 4 + i;
            if (gn < NN) {
                float4 o = make_float4(acc[i][0], acc[i][1], acc[i][2], acc[i][3]);
                if (c0 < 128) *(float4*)(g_Hd + (size_t)gn * 128 + c0) = o;
                else          *(float4*)(g_Hs + (size_t)gn * 128 + (c0 - 128)) = o;
            }
        }
    }
}

// ---------------- fused gather+aggregate (2 nodes/block, 4-wide, local scales) --
// layer==0: also stores s1/s2 for k_postlin (invc computed locally both layers).
__global__ __launch_bounds__(256) void k_agg(const float* __restrict__ preb, int layer) {
    int n = blockIdx.x * 2 + (threadIdx.x >> 7);
    int f = threadIdx.x & 127;     // 0..127
    int lo = g_rowptr[n], hi = g_rowptr[n + 1];
    float sum = 0.f, sq = 0.f;
    float mn = INFINITY, mx = -INFINITY;
    int p = lo;
    for (; p + 4 <= hi; p += 4) {
        int i0 = g_csrc[p], i1 = g_csrc[p + 1], i2 = g_csrc[p + 2], i3 = g_csrc[p + 3];
        float v0 = g_Hs[(size_t)i0 * 128 + f];
        float v1 = g_Hs[(size_t)i1 * 128 + f];
        float v2 = g_Hs[(size_t)i2 * 128 + f];
        float v3 = g_Hs[(size_t)i3 * 128 + f];
        sum += (v0 + v1) + (v2 + v3);
        sq  = fmaf(v0, v0, fmaf(v1, v1, fmaf(v2, v2, fmaf(v3, v3, sq))));
        mn = fminf(mn, fminf(fminf(v0, v1), fminf(v2, v3)));
        mx = fmaxf(mx, fmaxf(fmaxf(v0, v1), fmaxf(v2, v3)));
    }
    for (; p < hi; p++) {
        float v = g_Hs[(size_t)g_csrc[p] * 128 + f];
        sum += v; sq = fmaf(v, v, sq);
        mn = fminf(mn, v); mx = fmaxf(mx, v);
    }
    int deg = hi - lo;
    float dc   = fmaxf((float)deg, 1.f);
    float invc = 1.f / dc;
    if (layer == 0 && f == 0) {
        float avg = g_sumlog / (float)NN;
        float ld  = logf(dc + 1.f);
        g_s1[n] = ld / avg;
        g_s2[n] = avg / ld;
    }
    float c = g_Hd[(size_t)n * 128 + f] + preb[f];
    float mean, mnO, mxO, sd;
    if (deg > 0) {
        float ms  = sum * invc;
        float var = sq * invc - ms * ms;
        mean = c + ms; mnO = c + mn; mxO = c + mx;
        sd = sqrtf(fmaxf(var, 0.f) + 1e-5f);
    } else {
        mean = 0.f; mnO = 0.f; mxO = 0.f; sd = sqrtf(1e-5f);
    }
    int tt = f >> 6, ff = f & 63;
    size_t base = (size_t)n * 512 + tt * 256 + ff;
    g_agg[base]       = mean;
    g_agg[base + 64]  = mnO;
    g_agg[base + 128] = mxO;
    g_agg[base + 192] = sd;
}

// ---------------- fused post+lin GEMM (R10-proven) ------------------------------
#define TSTRIDE 4360   // tower stride in floats (4360 % 32 = 8 -> disjoint banks)
__global__ __launch_bounds__(256) void k_postlin(const float* __restrict__ postW,
                                                 const float* __restrict__ postb,
                                                 const float* __restrict__ linW,
                                                 const float* __restrict__ linb,
                                                 float* __restrict__ outp) {
    __shared__ float A13[2 * TSTRIDE]; // [tower][node(64)][k(68 pad)] — 34880 B
    __shared__ float Ws[64][64];       // weights tile — 16384 B
    int t  = threadIdx.x;
    int n0 = blockIdx.x * 64;
    int tx = t & 15, ty = t >> 4;
    int tc = tx >> 3;                  // tower for this thread's columns
    int abase = tc * TSTRIDE + ty * 4 * 68;   // this thread's 4 node rows

    float acc[4][4];
#pragma unroll
    for (int i = 0; i < 4; i++)
#pragma unroll
        for (int j = 0; j < 4; j++) acc[i][j] = 0.f;

    for (int ci = 0; ci < 13; ci++) {
        int kc = ci * 64;
        float4 va[8];
#pragma unroll
        for (int i = 0; i < 8; i++) {
            int u = t + 256 * i;
            int tw = u >> 10, node = (u >> 4) & 63, kq = u & 15;
            int gn = n0 + node;
            float4 v = make_float4(0.f, 0.f, 0.f, 0.f);
            if (gn < NN) {
                if (ci == 0) {
                    v = *(const float4*)(g_hA + (size_t)gn * 64 + kq * 4);
                } else {
                    int k = kc + kq * 4;
                    int j; float s = 1.f;
                    if (ci < 5)      { j = k - 64; }
                    else if (ci < 9) { j = k - 320; s = g_s1[gn]; }
                    else             { j = k - 576; s = g_s2[gn]; }
                    v = *(const float4*)(g_agg + (size_t)gn * 512 + tw * 256 + j);
                    v.x *= s; v.y *= s; v.z *= s; v.w *= s;
                }
            }
            va[i] = v;
        }
        float4 vb[4];
#pragma unroll
        for (int i = 0; i < 4; i++) {
            int u = t + 256 * i;
            int kk = u >> 4, cq = u & 15;
            int tw = cq >> 3, g = (cq * 4) & 31;
            vb[i] = *(const float4*)(postW + tw * 26624 + (kc + kk) * 32 + g);
        }
        __syncthreads();
#pragma unroll
        for (int i = 0; i < 8; i++) {
            int u = t + 256 * i;
            int tw = u >> 10, node = (u >> 4) & 63, kq = u & 15;
            *(float4*)&A13[tw * TSTRIDE + node * 68 + kq * 4] = va[i];
        }
#pragma unroll
        for (int i = 0; i < 4; i++) ((float4*)Ws)[t + 256 * i] = vb[i];
        __syncthreads();

#pragma unroll
        for (int kk = 0; kk < 64; kk += 4) {
            float4 ar4[4];
#pragma unroll
            for (int i = 0; i < 4; i++)
                ar4[i] = *(const float4*)&A13[abase + i * 68 + kk];
#pragma unroll
            for (int d = 0; d < 4; d++) {
                float4 b4 = *(const float4*)&Ws[kk + d][tx * 4];
                float br[4] = {b4.x, b4.y, b4.z, b4.w};
#pragma unroll
                for (int i = 0; i < 4; i++) {
                    float av = (&ar4[i].x)[d];
#pragma unroll
                    for (int j = 0; j < 4; j++) acc[i][j] = fmaf(av, br[j], acc[i][j]);
                }
            }
        }
        __syncthreads();
    }

    // -------- stage 2: P-tile -> smem (tower-0 area), multiply by linW --------
    float4 pbias = *(const float4*)(postb + tx * 4);
#pragma unroll
    for (int i = 0; i < 4; i++) {
        int r = (ty * 4 + i) * 68;
        A13[r + tx * 4 + 0] = acc[i][0] + pbias.x;
        A13[r + tx * 4 + 1] = acc[i][1] + pbias.y;
        A13[r + tx * 4 + 2] = acc[i][2] + pbias.z;
        A13[r + tx * 4 + 3] = acc[i][3] + pbias.w;
    }
#pragma unroll
    for (int i = 0; i < 4; i++)
        ((float4*)Ws)[t + 256 * i] = ((const float4*)linW)[t + 256 * i];
    __syncthreads();

    float acc2[4][4];
#pragma unroll
    for (int i = 0; i < 4; i++)
#pragma unroll
        for (int j = 0; j < 4; j++) acc2[i][j] = 0.f;

    int a2base = ty * 4 * 68;
#pragma unroll
    for (int kk = 0; kk < 64; kk += 4) {
        float4 ar4[4];
#pragma unroll
        for (int i = 0; i < 4; i++)
            ar4[i] = *(const float4*)&A13[a2base + i * 68 + kk];
#pragma unroll
        for (int d = 0; d < 4; d++) {
            float4 b4 = *(const float4*)&Ws[kk + d][tx * 4];
            float br[4] = {b4.x, b4.y, b4.z, b4.w};
#pragma unroll
            for (int i = 0; i < 4; i++) {
                float av = (&ar4[i].x)[d];
#pragma unroll
                for (int j = 0; j < 4; j++) acc2[i][j] = fmaf(av, br[j], acc2[i][j]);
            }
        }
    }

    float* target = outp ? outp : g_hB;
    float4 lbias = *(const float4*)(linb + tx * 4);
    float lsum[4] = {0.f, 0.f, 0.f, 0.f};
    float lsq[4]  = {0.f, 0.f, 0.f, 0.f};
#pragma unroll
    for (int i = 0; i < 4; i++) {
        int gn = n0 + ty * 4 + i;
        if (gn < NN) {
            float o0 = acc2[i][0] + lbias.x, o1 = acc2[i][1] + lbias.y;
            float o2 = acc2[i][2] + lbias.z, o3 = acc2[i][3] + lbias.w;
            *(float4*)(target + (size_t)gn * 64 + tx * 4) = make_float4(o0, o1, o2, o3);
            lsum[0] += o0; lsum[1] += o1; lsum[2] += o2; lsum[3] += o3;
            lsq[0] = fmaf(o0, o0, lsq[0]); lsq[1] = fmaf(o1, o1, lsq[1]);
            lsq[2] = fmaf(o2, o2, lsq[2]); lsq[3] = fmaf(o3, o3, lsq[3]);
        }
    }

    if (!outp) {   // fused BN stats (layer 1)
        __syncthreads();
        float* redS = &A13[TSTRIDE];   // tower-1 area, no longer needed
        float* redQ = &Ws[0][0];
#pragma unroll
        for (int j = 0; j < 4; j++) {
            redS[ty * 68 + tx * 4 + j] = lsum[j];
            redQ[ty * 68 + tx * 4 + j] = lsq[j];
        }
        __syncthreads();
        for (int o = 8; o > 0; o >>= 1) {
            if (ty < o) {
#pragma unroll
                for (int j = 0; j < 4; j++) {
                    redS[ty * 68 + tx * 4 + j] += redS[(ty + o) * 68 + tx * 4 + j];
                    redQ[ty * 68 + tx * 4 + j] += redQ[(ty + o) * 68 + tx * 4 + j];
                }
            }
            __syncthreads();
        }
        if (ty == 0) {
#pragma unroll
            for (int j = 0; j < 4; j++) {
                atomicAdd(&g_bnsum[tx * 4 + j], redS[tx * 4 + j]);
                atomicAdd(&g_bnsq[tx * 4 + j],  redQ[tx * 4 + j]);
            }
        }
    }
}

// ---------------- launch --------------------------------------------------------
extern "C" void kernel_launch(void* const* d_in, const int* in_sizes, int n_in,
                              void* d_out, int out_size) {
    const float* x       = (const float*)d_in[0];
    const float* embed_W = (const float*)d_in[1];
    const float* embed_b = (const float*)d_in[2];
    const float* pre_W1  = (const float*)d_in[3];
    const float* pre_b1  = (const float*)d_in[4];
    const float* post_W1 = (const float*)d_in[5];
    const float* post_b1 = (const float*)d_in[6];
    const float* lin_W1  = (const float*)d_in[7];
    const float* lin_b1  = (const float*)d_in[8];
    const float* bn_g    = (const float*)d_in[9];
    const float* bn_b    = (const float*)d_in[10];
    const float* pre_W2  = (const float*)d_in[11];
    const float* pre_b2  = (const float*)d_in[12];
    const float* post_W2 = (const float*)d_in[13];
    const float* post_b2 = (const float*)d_in[14];
    const float* lin_W2  = (const float*)d_in[15];
    const float* lin_b2  = (const float*)d_in[16];
    const int*   src     = (const int*)d_in[17];
    const int*   dst     = (const int*)d_in[18];
    float* out = (float*)d_out;

    const int GN256 = (NN + 255) / 256;
    const int GE256 = NE / 256;
    const int GT64  = (NN + 63) / 64;      // 782

    // graph structure (shared by both layers)
    k_init<<<GN256, 256>>>();
    k_degree<<<GE256, 256>>>(dst);
    k_logsum<<<GN256, 256>>>();
    k_scan<<<1, 1024>>>();
    k_scatter<<<GE256, 256>>>(src, dst);

    // weight packing (independent of embed inputs)
    k_preB2both<<<128, 256>>>(pre_W1, pre_W2);

    // ---- layer 1 (embed fused with Hd/Hs) ----
    k_embedhds<<<GT64, 256>>>(x, embed_W, embed_b);
    k_agg<<<NN / 2, 256>>>(pre_b1, 0);    // also stores s1/s2
    k_postlin<<<GT64, 256>>>(post_W1, post_b1, lin_W1, lin_b1, nullptr); // + BN stats

    // ---- layer 2 (k_hds1 computes BN scale/shift inline + applies BN+ReLU) ----
    k_hds1<<<GT64, 256>>>(bn_g, bn_b);
    k_agg<<<NN / 2, 256>>>(pre_b2, 1);
    k_postlin<<<GT64, 256>>>(post_W2, post_b2, lin_W2, lin_b2, out);
}

// round 14
// speedup vs baseline: 1.1572x; 1.0405x over previous
#include <cuda_runtime.h>
#include <math.h>

#define NN 50000
#define NE 800000
#define IND 128
#define NBLK 196   // ceil(NN/256)

// ---------------- scratch ------------------------------------------------------
__device__ float g_hA[NN * 64];        // layer input (embed out / post-BN)
__device__ float g_hB[NN * 64];        // layer1 output (pre-BN)
__device__ float g_Hd[NN * 128];       // h @ preW_top  (dst half)
__device__ float g_Hs[NN * 128];       // h @ preW_bot  (src half) — 25.6MB, L2-resident
__device__ float g_agg[NN * 512];      // per node: [t][stat(mean,min,max,std)][f]
__device__ int   g_deg[NN];
__device__ float g_s1[NN];
__device__ float g_s2[NN];
__device__ int   g_rowptr[NN + 1];
__device__ int   g_cursor[NN];
__device__ int   g_csrc[NE];
__device__ int   g_blksum[NBLK];
__device__ int   g_blkoff[NBLK];
__device__ float g_preB2a[64 * 256];   // layer1 packed preW  [k][c]
__device__ float g_preB2b[64 * 256];   // layer2 packed preW  [k][c]
__device__ float g_sumlog;
__device__ float g_bnsum[64];
__device__ float g_bnsq[64];

// ---------------- setup --------------------------------------------------------
__global__ void k_init() {
    int i = blockIdx.x * blockDim.x + threadIdx.x;
    if (i < NN) { g_deg[i] = 0; g_cursor[i] = 0; }
    if (i == 0) g_sumlog = 0.f;
    if (i < 64) { g_bnsum[i] = 0.f; g_bnsq[i] = 0.f; }
}

__global__ void k_degree(const int* __restrict__ dst) {
    int e = blockIdx.x * blockDim.x + threadIdx.x;
    if (e < NE) atomicAdd(&g_deg[dst[e]], 1);
}

// per-block degree sum + global log-sum
__global__ void k_blk() {
    __shared__ float slog[256];
    __shared__ int   sdeg[256];
    int t = threadIdx.x;
    int i = blockIdx.x * 256 + t;
    int d = (i < NN) ? g_deg[i] : 0;
    slog[t] = (i < NN) ? logf((float)d + 1.f) : 0.f;
    sdeg[t] = d;
    __syncthreads();
    for (int o = 128; o > 0; o >>= 1) {
        if (t < o) { slog[t] += slog[t + o]; sdeg[t] += sdeg[t + o]; }
        __syncthreads();
    }
    if (t == 0) {
        atomicAdd(&g_sumlog, slog[0]);
        g_blksum[blockIdx.x] = sdeg[0];
    }
}

// exclusive scan of NBLK block sums (single tiny block)
__global__ void k_scanblk() {
    __shared__ int s[256];
    int t = threadIdx.x;
    s[t] = (t < NBLK) ? g_blksum[t] : 0;
    __syncthreads();
    for (int o = 1; o < 256; o <<= 1) {
        int v = (t >= o) ? s[t - o] : 0;
        __syncthreads();
        s[t] += v;
        __syncthreads();
    }
    if (t < NBLK) g_blkoff[t] = (t == 0) ? 0 : s[t - 1];
}

// per-block 256-wide inclusive scan + block offset -> rowptr
__global__ void k_rowptr() {
    __shared__ int s[256];
    int t = threadIdx.x;
    int i = blockIdx.x * 256 + t;
    int d = (i < NN) ? g_deg[i] : 0;
    s[t] = d;
    __syncthreads();
    for (int o = 1; o < 256; o <<= 1) {
        int v = (t >= o) ? s[t - o] : 0;
        __syncthreads();
        s[t] += v;
        __syncthreads();
    }
    int off = g_blkoff[blockIdx.x];
    if (i < NN) g_rowptr[i] = off + s[t] - d;     // exclusive
    if (i == NN - 1) g_rowptr[NN] = off + s[t];   // total = NE
}

__global__ void k_scatter(const int* __restrict__ src, const int* __restrict__ dst) {
    int e = blockIdx.x * blockDim.x + threadIdx.x;
    if (e >= NE) return;
    int d = dst[e];
    int pos = g_rowptr[d] + atomicAdd(&g_cursor[d], 1);
    g_csrc[pos] = src[e];
}

// pack both layers' preW (T,128,64) into [64][256]: col c: half=c>>7, j=c&127
__global__ void k_preB2both(const float* __restrict__ preW1,
                            const float* __restrict__ preW2) {
    int i = blockIdx.x * blockDim.x + threadIdx.x;
    if (i >= 2 * 64 * 256) return;
    int which = i >> 14;               // 0: layer1, 1: layer2
    int u = i & 16383;
    int k = u >> 8, c = u & 255;
    int half = c >> 7, j = c & 127;
    int t = j >> 6, f = j & 63;
    const float* w = which ? preW2 : preW1;
    float* o = which ? g_preB2b : g_preB2a;
    o[u] = w[t * 8192 + (half * 64 + k) * 64 + f];
}

// ---------------- fused embed + layer-1 Hd/Hs -----------------------------------
__global__ __launch_bounds__(256) void k_embedhds(const float* __restrict__ x,
                                                  const float* __restrict__ W,
                                                  const float* __restrict__ b) {
    __shared__ float Xs[128][64];      // stage A: x-tile [k][row]; stage B rows 0-63: h [k][node]
    __shared__ float Ws[128][64];      // stage A: embed_W [k][col]; stage B rows 0-63: preB chunk
    int t  = threadIdx.x;
    int n0 = blockIdx.x * 64;

    for (int i = t; i < 2048; i += 256)
        ((float4*)Ws)[i] = ((const float4*)W)[i];

    int row = t & 63, kq = t >> 6;
    int gr = n0 + row;
#pragma unroll
    for (int j = 0; j < 8; j++) {
        int k = kq * 32 + j * 4;
        float4 v = make_float4(0.f, 0.f, 0.f, 0.f);
        if (gr < NN) v = *(const float4*)(x + (size_t)gr * IND + k);
        Xs[k][row] = v.x; Xs[k + 1][row] = v.y; Xs[k + 2][row] = v.z; Xs[k + 3][row] = v.w;
    }
    __syncthreads();

    int tx = t & 15, ty = t >> 4;
    float acc[4][4];
#pragma unroll
    for (int i = 0; i < 4; i++)
#pragma unroll
        for (int j = 0; j < 4; j++) acc[i][j] = 0.f;

#pragma unroll 8
    for (int k = 0; k < 128; k++) {
        float4 a  = *(const float4*)&Xs[k][ty * 4];
        float4 b4 = *(const float4*)&Ws[k][tx * 4];
        float ar[4] = {a.x, a.y, a.z, a.w};
        float br[4] = {b4.x, b4.y, b4.z, b4.w};
#pragma unroll
        for (int i = 0; i < 4; i++)
#pragma unroll
            for (int j = 0; j < 4; j++) acc[i][j] = fmaf(ar[i], br[j], acc[i][j]);
    }

    float4 bias = *(const float4*)(b + tx * 4);
    __syncthreads();   // all embed reads of Xs done before overwrite
#pragma unroll
    for (int i = 0; i < 4; i++) {
        int gn = n0 + ty * 4 + i;
        float o0 = acc[i][0] + bias.x, o1 = acc[i][1] + bias.y;
        float o2 = acc[i][2] + bias.z, o3 = acc[i][3] + bias.w;
        if (gn < NN)
            *(float4*)(g_hA + (size_t)gn * 64 + tx * 4) = make_float4(o0, o1, o2, o3);
        int node = ty * 4 + i;
        Xs[tx * 4 + 0][node] = o0;
        Xs[tx * 4 + 1][node] = o1;
        Xs[tx * 4 + 2][node] = o2;
        Xs[tx * 4 + 3][node] = o3;
    }

    // ---- stage B: proven hds column-group loop (h in Xs rows 0-63) ----
    float (*Bs)[64] = (float(*)[64])Ws;
    for (int cg = 0; cg < 4; cg++) {
        __syncthreads();
#pragma unroll
        for (int i = 0; i < 4; i++) {
            int u = t + 256 * i;
            int k = u >> 4, cq = u & 15;
            *(float4*)&Bs[k][cq * 4] = *(const float4*)(g_preB2a + k * 256 + cg * 64 + cq * 4);
        }
        __syncthreads();

        float acc2[4][4];
#pragma unroll
        for (int i = 0; i < 4; i++)
#pragma unroll
            for (int j = 0; j < 4; j++) acc2[i][j] = 0.f;

#pragma unroll 8
        for (int k = 0; k < 64; k++) {
            float4 a  = *(const float4*)&Xs[k][ty * 4];
            float4 b4 = *(const float4*)&Bs[k][tx * 4];
            float ar[4] = {a.x, a.y, a.z, a.w};
            float br[4] = {b4.x, b4.y, b4.z, b4.w};
#pragma unroll
            for (int i = 0; i < 4; i++)
#pragma unroll
                for (int j = 0; j < 4; j++) acc2[i][j] = fmaf(ar[i], br[j], acc2[i][j]);
        }

        int c0 = cg * 64 + tx * 4;
#pragma unroll
        for (int i = 0; i < 4; i++) {
            int gn = n0 + ty * 4 + i;
            if (gn < NN) {
                float4 o = make_float4(acc2[i][0], acc2[i][1], acc2[i][2], acc2[i][3]);
                if (c0 < 128) *(float4*)(g_Hd + (size_t)gn * 128 + c0) = o;
                else          *(float4*)(g_Hs + (size_t)gn * 128 + (c0 - 128)) = o;
            }
        }
    }
}

// ---------------- layer-2 Hd/Hs GEMM with inline BN+ReLU ------------------------
__global__ __launch_bounds__(256) void k_hds1(const float* __restrict__ gamma,
                                              const float* __restrict__ beta) {
    __shared__ float Xs[64][64];   // [k][node]
    __shared__ float Bs[64][64];   // [k][c]
    __shared__ float bsc[64], bsh[64];
    int t  = threadIdx.x;
    int n0 = blockIdx.x * 64;

    if (t < 64) {
        float mu  = g_bnsum[t] / (float)NN;
        float var = g_bnsq[t] / (float)NN - mu * mu;
        float sc  = gamma[t] * rsqrtf(var + 1e-5f);
        bsc[t] = sc;
        bsh[t] = beta[t] - mu * sc;
    }
    __syncthreads();

    int node = t & 63, kq = t >> 6;
    int gr = n0 + node;
#pragma unroll
    for (int j = 0; j < 4; j++) {
        int k = kq * 16 + j * 4;
        float4 v = make_float4(0.f, 0.f, 0.f, 0.f);
        if (gr < NN) {
            float4 hv = *(const float4*)(g_hB + (size_t)gr * 64 + k);
            v.x = fmaxf(hv.x * bsc[k]     + bsh[k],     0.f);
            v.y = fmaxf(hv.y * bsc[k + 1] + bsh[k + 1], 0.f);
            v.z = fmaxf(hv.z * bsc[k + 2] + bsh[k + 2], 0.f);
            v.w = fmaxf(hv.w * bsc[k + 3] + bsh[k + 3], 0.f);
            *(float4*)(g_hA + (size_t)gr * 64 + k) = v;   // layer-2 h input
        }
        Xs[k][node] = v.x; Xs[k + 1][node] = v.y; Xs[k + 2][node] = v.z; Xs[k + 3][node] = v.w;
    }

    int tx = t & 15, ty = t >> 4;

    for (int cg = 0; cg < 4; cg++) {
        __syncthreads();
#pragma unroll
        for (int i = 0; i < 4; i++) {
            int u = t + 256 * i;
            int k = u >> 4, cq = u & 15;
            *(float4*)&Bs[k][cq * 4] = *(const float4*)(g_preB2b + k * 256 + cg * 64 + cq * 4);
        }
        __syncthreads();

        float acc[4][4];
#pragma unroll
        for (int i = 0; i < 4; i++)
#pragma unroll
            for (int j = 0; j < 4; j++) acc[i][j] = 0.f;

#pragma unroll 8
        for (int k = 0; k < 64; k++) {
            float4 a  = *(const float4*)&Xs[k][ty * 4];
            float4 b4 = *(const float4*)&Bs[k][tx * 4];
            float ar[4] = {a.x, a.y, a.z, a.w};
            float br[4] = {b4.x, b4.y, b4.z, b4.w};
#pragma unroll
            for (int i = 0; i < 4; i++)
#pragma unroll
                for (int j = 0; j < 4; j++) acc[i][j] = fmaf(ar[i], br[j], acc[i][j]);
        }

        int c0 = cg * 64 + tx * 4;
#pragma unroll
        for (int i = 0; i < 4; i++) {
            int gn = n0 + ty * 4 + i;
            if (gn < NN) {
                float4 o = make_float4(acc[i][0], acc[i][1], acc[i][2], acc[i][3]);
                if (c0 < 128) *(float4*)(g_Hd + (size_t)gn * 128 + c0) = o;
                else          *(float4*)(g_Hs + (size_t)gn * 128 + (c0 - 128)) = o;
            }
        }
    }
}

// ---------------- fused gather+aggregate (2 nodes/block, 4-wide, local scales) --
__global__ __launch_bounds__(256) void k_agg(const float* __restrict__ preb, int layer) {
    int n = blockIdx.x * 2 + (threadIdx.x >> 7);
    int f = threadIdx.x & 127;     // 0..127
    int lo = g_rowptr[n], hi = g_rowptr[n + 1];
    float sum = 0.f, sq = 0.f;
    float mn = INFINITY, mx = -INFINITY;
    int p = lo;
    for (; p + 4 <= hi; p += 4) {
        int i0 = g_csrc[p], i1 = g_csrc[p + 1], i2 = g_csrc[p + 2], i3 = g_csrc[p + 3];
        float v0 = g_Hs[(size_t)i0 * 128 + f];
        float v1 = g_Hs[(size_t)i1 * 128 + f];
        float v2 = g_Hs[(size_t)i2 * 128 + f];
        float v3 = g_Hs[(size_t)i3 * 128 + f];
        sum += (v0 + v1) + (v2 + v3);
        sq  = fmaf(v0, v0, fmaf(v1, v1, fmaf(v2, v2, fmaf(v3, v3, sq))));
        mn = fminf(mn, fminf(fminf(v0, v1), fminf(v2, v3)));
        mx = fmaxf(mx, fmaxf(fmaxf(v0, v1), fmaxf(v2, v3)));
    }
    for (; p < hi; p++) {
        float v = g_Hs[(size_t)g_csrc[p] * 128 + f];
        sum += v; sq = fmaf(v, v, sq);
        mn = fminf(mn, v); mx = fmaxf(mx, v);
    }
    int deg = hi - lo;
    float dc   = fmaxf((float)deg, 1.f);
    float invc = 1.f / dc;
    if (layer == 0 && f == 0) {
        float avg = g_sumlog / (float)NN;
        float ld  = logf(dc + 1.f);
        g_s1[n] = ld / avg;
        g_s2[n] = avg / ld;
    }
    float c = g_Hd[(size_t)n * 128 + f] + preb[f];
    float mean, mnO, mxO, sd;
    if (deg > 0) {
        float ms  = sum * invc;
        float var = sq * invc - ms * ms;
        mean = c + ms; mnO = c + mn; mxO = c + mx;
        sd = sqrtf(fmaxf(var, 0.f) + 1e-5f);
    } else {
        mean = 0.f; mnO = 0.f; mxO = 0.f; sd = sqrtf(1e-5f);
    }
    int tt = f >> 6, ff = f & 63;
    size_t base = (size_t)n * 512 + tt * 256 + ff;
    g_agg[base]       = mean;
    g_agg[base + 64]  = mnO;
    g_agg[base + 128] = mxO;
    g_agg[base + 192] = sd;
}

// ---------------- fused post+lin GEMM (R10-proven) ------------------------------
#define TSTRIDE 4360   // tower stride in floats (4360 % 32 = 8 -> disjoint banks)
__global__ __launch_bounds__(256) void k_postlin(const float* __restrict__ postW,
                                                 const float* __restrict__ postb,
                                                 const float* __restrict__ linW,
                                                 const float* __restrict__ linb,
                                                 float* __restrict__ outp) {
    __shared__ float A13[2 * TSTRIDE]; // [tower][node(64)][k(68 pad)] — 34880 B
    __shared__ float Ws[64][64];       // weights tile — 16384 B
    int t  = threadIdx.x;
    int n0 = blockIdx.x * 64;
    int tx = t & 15, ty = t >> 4;
    int tc = tx >> 3;                  // tower for this thread's columns
    int abase = tc * TSTRIDE + ty * 4 * 68;   // this thread's 4 node rows

    float acc[4][4];
#pragma unroll
    for (int i = 0; i < 4; i++)
#pragma unroll
        for (int j = 0; j < 4; j++) acc[i][j] = 0.f;

    for (int ci = 0; ci < 13; ci++) {
        int kc = ci * 64;
        float4 va[8];
#pragma unroll
        for (int i = 0; i < 8; i++) {
            int u = t + 256 * i;
            int tw = u >> 10, node = (u >> 4) & 63, kq = u & 15;
            int gn = n0 + node;
            float4 v = make_float4(0.f, 0.f, 0.f, 0.f);
            if (gn < NN) {
                if (ci == 0) {
                    v = *(const float4*)(g_hA + (size_t)gn * 64 + kq * 4);
                } else {
                    int k = kc + kq * 4;
                    int j; float s = 1.f;
                    if (ci < 5)      { j = k - 64; }
                    else if (ci < 9) { j = k - 320; s = g_s1[gn]; }
                    else             { j = k - 576; s = g_s2[gn]; }
                    v = *(const float4*)(g_agg + (size_t)gn * 512 + tw * 256 + j);
                    v.x *= s; v.y *= s; v.z *= s; v.w *= s;
                }
            }
            va[i] = v;
        }
        float4 vb[4];
#pragma unroll
        for (int i = 0; i < 4; i++) {
            int u = t + 256 * i;
            int kk = u >> 4, cq = u & 15;
            int tw = cq >> 3, g = (cq * 4) & 31;
            vb[i] = *(const float4*)(postW + tw * 26624 + (kc + kk) * 32 + g);
        }
        __syncthreads();
#pragma unroll
        for (int i = 0; i < 8; i++) {
            int u = t + 256 * i;
            int tw = u >> 10, node = (u >> 4) & 63, kq = u & 15;
            *(float4*)&A13[tw * TSTRIDE + node * 68 + kq * 4] = va[i];
        }
#pragma unroll
        for (int i = 0; i < 4; i++) ((float4*)Ws)[t + 256 * i] = vb[i];
        __syncthreads();

#pragma unroll
        for (int kk = 0; kk < 64; kk += 4) {
            float4 ar4[4];
#pragma unroll
            for (int i = 0; i < 4; i++)
                ar4[i] = *(const float4*)&A13[abase + i * 68 + kk];
#pragma unroll
            for (int d = 0; d < 4; d++) {
                float4 b4 = *(const float4*)&Ws[kk + d][tx * 4];
                float br[4] = {b4.x, b4.y, b4.z, b4.w};
#pragma unroll
                for (int i = 0; i < 4; i++) {
                    float av = (&ar4[i].x)[d];
#pragma unroll
                    for (int j = 0; j < 4; j++) acc[i][j] = fmaf(av, br[j], acc[i][j]);
                }
            }
        }
        __syncthreads();
    }

    // -------- stage 2: P-tile -> smem (tower-0 area), multiply by linW --------
    float4 pbias = *(const float4*)(postb + tx * 4);
#pragma unroll
    for (int i = 0; i < 4; i++) {
        int r = (ty * 4 + i) * 68;
        A13[r + tx * 4 + 0] = acc[i][0] + pbias.x;
        A13[r + tx * 4 + 1] = acc[i][1] + pbias.y;
        A13[r + tx * 4 + 2] = acc[i][2] + pbias.z;
        A13[r + tx * 4 + 3] = acc[i][3] + pbias.w;
    }
#pragma unroll
    for (int i = 0; i < 4; i++)
        ((float4*)Ws)[t + 256 * i] = ((const float4*)linW)[t + 256 * i];
    __syncthreads();

    float acc2[4][4];
#pragma unroll
    for (int i = 0; i < 4; i++)
#pragma unroll
        for (int j = 0; j < 4; j++) acc2[i][j] = 0.f;

    int a2base = ty * 4 * 68;
#pragma unroll
    for (int kk = 0; kk < 64; kk += 4) {
        float4 ar4[4];
#pragma unroll
        for (int i = 0; i < 4; i++)
            ar4[i] = *(const float4*)&A13[a2base + i * 68 + kk];
#pragma unroll
        for (int d = 0; d < 4; d++) {
            float4 b4 = *(const float4*)&Ws[kk + d][tx * 4];
            float br[4] = {b4.x, b4.y, b4.z, b4.w};
#pragma unroll
            for (int i = 0; i < 4; i++) {
                float av = (&ar4[i].x)[d];
#pragma unroll
                for (int j = 0; j < 4; j++) acc2[i][j] = fmaf(av, br[j], acc2[i][j]);
            }
        }
    }

    float* target = outp ? outp : g_hB;
    float4 lbias = *(const float4*)(linb + tx * 4);
    float lsum[4] = {0.f, 0.f, 0.f, 0.f};
    float lsq[4]  = {0.f, 0.f, 0.f, 0.f};
#pragma unroll
    for (int i = 0; i < 4; i++) {
        int gn = n0 + ty * 4 + i;
        if (gn < NN) {
            float o0 = acc2[i][0] + lbias.x, o1 = acc2[i][1] + lbias.y;
            float o2 = acc2[i][2] + lbias.z, o3 = acc2[i][3] + lbias.w;
            *(float4*)(target + (size_t)gn * 64 + tx * 4) = make_float4(o0, o1, o2, o3);
            lsum[0] += o0; lsum[1] += o1; lsum[2] += o2; lsum[3] += o3;
            lsq[0] = fmaf(o0, o0, lsq[0]); lsq[1] = fmaf(o1, o1, lsq[1]);
            lsq[2] = fmaf(o2, o2, lsq[2]); lsq[3] = fmaf(o3, o3, lsq[3]);
        }
    }

    if (!outp) {   // fused BN stats (layer 1)
        __syncthreads();
        float* redS = &A13[TSTRIDE];
        float* redQ = &Ws[0][0];
#pragma unroll
        for (int j = 0; j < 4; j++) {
            redS[ty * 68 + tx * 4 + j] = lsum[j];
            redQ[ty * 68 + tx * 4 + j] = lsq[j];
        }
        __syncthreads();
        for (int o = 8; o > 0; o >>= 1) {
            if (ty < o) {
#pragma unroll
                for (int j = 0; j < 4; j++) {
                    redS[ty * 68 + tx * 4 + j] += redS[(ty + o) * 68 + tx * 4 + j];
                    redQ[ty * 68 + tx * 4 + j] += redQ[(ty + o) * 68 + tx * 4 + j];
                }
            }
            __syncthreads();
        }
        if (ty == 0) {
#pragma unroll
            for (int j = 0; j < 4; j++) {
                atomicAdd(&g_bnsum[tx * 4 + j], redS[tx * 4 + j]);
                atomicAdd(&g_bnsq[tx * 4 + j],  redQ[tx * 4 + j]);
            }
        }
    }
}

// ---------------- launch --------------------------------------------------------
extern "C" void kernel_launch(void* const* d_in, const int* in_sizes, int n_in,
                              void* d_out, int out_size) {
    const float* x       = (const float*)d_in[0];
    const float* embed_W = (const float*)d_in[1];
    const float* embed_b = (const float*)d_in[2];
    const float* pre_W1  = (const float*)d_in[3];
    const float* pre_b1  = (const float*)d_in[4];
    const float* post_W1 = (const float*)d_in[5];
    const float* post_b1 = (const float*)d_in[6];
    const float* lin_W1  = (const float*)d_in[7];
    const float* lin_b1  = (const float*)d_in[8];
    const float* bn_g    = (const float*)d_in[9];
    const float* bn_b    = (const float*)d_in[10];
    const float* pre_W2  = (const float*)d_in[11];
    const float* pre_b2  = (const float*)d_in[12];
    const float* post_W2 = (const float*)d_in[13];
    const float* post_b2 = (const float*)d_in[14];
    const float* lin_W2  = (const float*)d_in[15];
    const float* lin_b2  = (const float*)d_in[16];
    const int*   src     = (const int*)d_in[17];
    const int*   dst     = (const int*)d_in[18];
    float* out = (float*)d_out;

    const int GN256 = (NN + 255) / 256;    // 196 = NBLK
    const int GE256 = NE / 256;
    const int GT64  = (NN + 63) / 64;      // 782

    // graph structure (shared by both layers) — parallel 3-phase scan
    k_init<<<GN256, 256>>>();
    k_degree<<<GE256, 256>>>(dst);
    k_blk<<<GN256, 256>>>();
    k_scanblk<<<1, 256>>>();
    k_rowptr<<<GN256, 256>>>();
    k_scatter<<<GE256, 256>>>(src, dst);

    // weight packing (independent of embed inputs)
    k_preB2both<<<128, 256>>>(pre_W1, pre_W2);

    // ---- layer 1 (embed fused with Hd/Hs) ----
    k_embedhds<<<GT64, 256>>>(x, embed_W, embed_b);
    k_agg<<<NN / 2, 256>>>(pre_b1, 0);    // also stores s1/s2
    k_postlin<<<GT64, 256>>>(post_W1, post_b1, lin_W1, lin_b1, nullptr); // + BN stats

    // ---- layer 2 (k_hds1 computes BN scale/shift inline + applies BN+ReLU) ----
    k_hds1<<<GT64, 256>>>(bn_g, bn_b);
    k_agg<<<NN / 2, 256>>>(pre_b2, 1);
    k_postlin<<<GT64, 256>>>(post_W2, post_b2, lin_W2, lin_b2, out);
}

// round 15
// speedup vs baseline: 1.3266x; 1.1464x over previous
#include <cuda_runtime.h>
#include <math.h>

#define NN 50000
#define NE 800000
#define IND 128
#define NBLK 196   // ceil(NN/256)

// ---------------- scratch ------------------------------------------------------
__device__ float g_hA[NN * 64];        // layer input (embed out / post-BN)
__device__ float g_hB[NN * 64];        // layer1 output (pre-BN)
__device__ float g_Hd[NN * 128];       // h @ preW_top  (dst half)
__device__ float g_Hs[NN * 128];       // h @ preW_bot  (src half) — 25.6MB, L2-resident
__device__ float g_agg[NN * 512];      // per node: [t][stat(mean,min,max,std)][f]
__device__ int   g_deg[NN];
__device__ float g_s1[NN];
__device__ float g_s2[NN];
__device__ int   g_rowptr[NN + 1];
__device__ int   g_cursor[NN];
__device__ int   g_csrc[NE];
__device__ int   g_blksum[NBLK];
__device__ int   g_blkoff[NBLK];
__device__ float g_preB2a[64 * 256];   // layer1 packed preW  [k][c]
__device__ float g_preB2b[64 * 256];   // layer2 packed preW  [k][c]
__device__ float g_sumlog;
__device__ float g_bnsum[64];
__device__ float g_bnsq[64];

// ---------------- setup --------------------------------------------------------
__global__ void k_init() {
    int i = blockIdx.x * blockDim.x + threadIdx.x;
    if (i < NN) { g_deg[i] = 0; g_cursor[i] = 0; }
    if (i == 0) g_sumlog = 0.f;
    if (i < 64) { g_bnsum[i] = 0.f; g_bnsq[i] = 0.f; }
}

__global__ void k_degree(const int* __restrict__ dst) {
    int e = blockIdx.x * blockDim.x + threadIdx.x;
    if (e < NE) atomicAdd(&g_deg[dst[e]], 1);
}

// per-block degree sum + global log-sum
__global__ void k_blk() {
    __shared__ float slog[256];
    __shared__ int   sdeg[256];
    int t = threadIdx.x;
    int i = blockIdx.x * 256 + t;
    int d = (i < NN) ? g_deg[i] : 0;
    slog[t] = (i < NN) ? logf((float)d + 1.f) : 0.f;
    sdeg[t] = d;
    __syncthreads();
    for (int o = 128; o > 0; o >>= 1) {
        if (t < o) { slog[t] += slog[t + o]; sdeg[t] += sdeg[t + o]; }
        __syncthreads();
    }
    if (t == 0) {
        atomicAdd(&g_sumlog, slog[0]);
        g_blksum[blockIdx.x] = sdeg[0];
    }
}

// exclusive scan of NBLK block sums (single tiny block)
__global__ void k_scanblk() {
    __shared__ int s[256];
    int t = threadIdx.x;
    s[t] = (t < NBLK) ? g_blksum[t] : 0;
    __syncthreads();
    for (int o = 1; o < 256; o <<= 1) {
        int v = (t >= o) ? s[t - o] : 0;
        __syncthreads();
        s[t] += v;
        __syncthreads();
    }
    if (t < NBLK) g_blkoff[t] = (t == 0) ? 0 : s[t - 1];
}

// per-block 256-wide inclusive scan + block offset -> rowptr
__global__ void k_rowptr() {
    __shared__ int s[256];
    int t = threadIdx.x;
    int i = blockIdx.x * 256 + t;
    int d = (i < NN) ? g_deg[i] : 0;
    s[t] = d;
    __syncthreads();
    for (int o = 1; o < 256; o <<= 1) {
        int v = (t >= o) ? s[t - o] : 0;
        __syncthreads();
        s[t] += v;
        __syncthreads();
    }
    int off = g_blkoff[blockIdx.x];
    if (i < NN) g_rowptr[i] = off + s[t] - d;     // exclusive
    if (i == NN - 1) g_rowptr[NN] = off + s[t];   // total = NE
}

__global__ void k_scatter(const int* __restrict__ src, const int* __restrict__ dst) {
    int e = blockIdx.x * blockDim.x + threadIdx.x;
    if (e >= NE) return;
    int d = dst[e];
    int pos = g_rowptr[d] + atomicAdd(&g_cursor[d], 1);
    g_csrc[pos] = src[e];
}

// pack both layers' preW (T,128,64) into [64][256]: col c: half=c>>7, j=c&127
__global__ void k_preB2both(const float* __restrict__ preW1,
                            const float* __restrict__ preW2) {
    int i = blockIdx.x * blockDim.x + threadIdx.x;
    if (i >= 2 * 64 * 256) return;
    int which = i >> 14;               // 0: layer1, 1: layer2
    int u = i & 16383;
    int k = u >> 8, c = u & 255;
    int half = c >> 7, j = c & 127;
    int t = j >> 6, f = j & 63;
    const float* w = which ? preW2 : preW1;
    float* o = which ? g_preB2b : g_preB2a;
    o[u] = w[t * 8192 + (half * 64 + k) * 64 + f];
}

// ---------------- fused embed + layer-1 Hd/Hs -----------------------------------
__global__ __launch_bounds__(256) void k_embedhds(const float* __restrict__ x,
                                                  const float* __restrict__ W,
                                                  const float* __restrict__ b) {
    __shared__ float Xs[128][64];      // stage A: x-tile [k][row]; stage B rows 0-63: h [k][node]
    __shared__ float Ws[128][64];      // stage A: embed_W [k][col]; stage B rows 0-63: preB chunk
    int t  = threadIdx.x;
    int n0 = blockIdx.x * 64;

    for (int i = t; i < 2048; i += 256)
        ((float4*)Ws)[i] = ((const float4*)W)[i];

    int row = t & 63, kq = t >> 6;
    int gr = n0 + row;
#pragma unroll
    for (int j = 0; j < 8; j++) {
        int k = kq * 32 + j * 4;
        float4 v = make_float4(0.f, 0.f, 0.f, 0.f);
        if (gr < NN) v = *(const float4*)(x + (size_t)gr * IND + k);
        Xs[k][row] = v.x; Xs[k + 1][row] = v.y; Xs[k + 2][row] = v.z; Xs[k + 3][row] = v.w;
    }
    __syncthreads();

    int tx = t & 15, ty = t >> 4;
    float acc[4][4];
#pragma unroll
    for (int i = 0; i < 4; i++)
#pragma unroll
        for (int j = 0; j < 4; j++) acc[i][j] = 0.f;

#pragma unroll 8
    for (int k = 0; k < 128; k++) {
        float4 a  = *(const float4*)&Xs[k][ty * 4];
        float4 b4 = *(const float4*)&Ws[k][tx * 4];
        float ar[4] = {a.x, a.y, a.z, a.w};
        float br[4] = {b4.x, b4.y, b4.z, b4.w};
#pragma unroll
        for (int i = 0; i < 4; i++)
#pragma unroll
            for (int j = 0; j < 4; j++) acc[i][j] = fmaf(ar[i], br[j], acc[i][j]);
    }

    float4 bias = *(const float4*)(b + tx * 4);
    __syncthreads();   // all embed reads of Xs done before overwrite
#pragma unroll
    for (int i = 0; i < 4; i++) {
        int gn = n0 + ty * 4 + i;
        float o0 = acc[i][0] + bias.x, o1 = acc[i][1] + bias.y;
        float o2 = acc[i][2] + bias.z, o3 = acc[i][3] + bias.w;
        if (gn < NN)
            *(float4*)(g_hA + (size_t)gn * 64 + tx * 4) = make_float4(o0, o1, o2, o3);
        int node = ty * 4 + i;
        Xs[tx * 4 + 0][node] = o0;
        Xs[tx * 4 + 1][node] = o1;
        Xs[tx * 4 + 2][node] = o2;
        Xs[tx * 4 + 3][node] = o3;
    }

    // ---- stage B: proven hds column-group loop (h in Xs rows 0-63) ----
    float (*Bs)[64] = (float(*)[64])Ws;
    for (int cg = 0; cg < 4; cg++) {
        __syncthreads();
#pragma unroll
        for (int i = 0; i < 4; i++) {
            int u = t + 256 * i;
            int k = u >> 4, cq = u & 15;
            *(float4*)&Bs[k][cq * 4] = *(const float4*)(g_preB2a + k * 256 + cg * 64 + cq * 4);
        }
        __syncthreads();

        float acc2[4][4];
#pragma unroll
        for (int i = 0; i < 4; i++)
#pragma unroll
            for (int j = 0; j < 4; j++) acc2[i][j] = 0.f;

#pragma unroll 8
        for (int k = 0; k < 64; k++) {
            float4 a  = *(const float4*)&Xs[k][ty * 4];
            float4 b4 = *(const float4*)&Bs[k][tx * 4];
            float ar[4] = {a.x, a.y, a.z, a.w};
            float br[4] = {b4.x, b4.y, b4.z, b4.w};
#pragma unroll
            for (int i = 0; i < 4; i++)
#pragma unroll
                for (int j = 0; j < 4; j++) acc2[i][j] = fmaf(ar[i], br[j], acc2[i][j]);
        }

        int c0 = cg * 64 + tx * 4;
#pragma unroll
        for (int i = 0; i < 4; i++) {
            int gn = n0 + ty * 4 + i;
            if (gn < NN) {
                float4 o = make_float4(acc2[i][0], acc2[i][1], acc2[i][2], acc2[i][3]);
                if (c0 < 128) *(float4*)(g_Hd + (size_t)gn * 128 + c0) = o;
                else          *(float4*)(g_Hs + (size_t)gn * 128 + (c0 - 128)) = o;
            }
        }
    }
}

// ---------------- layer-2 Hd/Hs GEMM with inline BN+ReLU ------------------------
__global__ __launch_bounds__(256) void k_hds1(const float* __restrict__ gamma,
                                              const float* __restrict__ beta) {
    __shared__ float Xs[64][64];   // [k][node]
    __shared__ float Bs[64][64];   // [k][c]
    __shared__ float bsc[64], bsh[64];
    int t  = threadIdx.x;
    int n0 = blockIdx.x * 64;

    if (t < 64) {
        float mu  = g_bnsum[t] / (float)NN;
        float var = g_bnsq[t] / (float)NN - mu * mu;
        float sc  = gamma[t] * rsqrtf(var + 1e-5f);
        bsc[t] = sc;
        bsh[t] = beta[t] - mu * sc;
    }
    __syncthreads();

    int node = t & 63, kq = t >> 6;
    int gr = n0 + node;
#pragma unroll
    for (int j = 0; j < 4; j++) {
        int k = kq * 16 + j * 4;
        float4 v = make_float4(0.f, 0.f, 0.f, 0.f);
        if (gr < NN) {
            float4 hv = *(const float4*)(g_hB + (size_t)gr * 64 + k);
            v.x = fmaxf(hv.x * bsc[k]     + bsh[k],     0.f);
            v.y = fmaxf(hv.y * bsc[k + 1] + bsh[k + 1], 0.f);
            v.z = fmaxf(hv.z * bsc[k + 2] + bsh[k + 2], 0.f);
            v.w = fmaxf(hv.w * bsc[k + 3] + bsh[k + 3], 0.f);
            *(float4*)(g_hA + (size_t)gr * 64 + k) = v;   // layer-2 h input
        }
        Xs[k][node] = v.x; Xs[k + 1][node] = v.y; Xs[k + 2][node] = v.z; Xs[k + 3][node] = v.w;
    }

    int tx = t & 15, ty = t >> 4;

    for (int cg = 0; cg < 4; cg++) {
        __syncthreads();
#pragma unroll
        for (int i = 0; i < 4; i++) {
            int u = t + 256 * i;
            int k = u >> 4, cq = u & 15;
            *(float4*)&Bs[k][cq * 4] = *(const float4*)(g_preB2b + k * 256 + cg * 64 + cq * 4);
        }
        __syncthreads();

        float acc[4][4];
#pragma unroll
        for (int i = 0; i < 4; i++)
#pragma unroll
            for (int j = 0; j < 4; j++) acc[i][j] = 0.f;

#pragma unroll 8
        for (int k = 0; k < 64; k++) {
            float4 a  = *(const float4*)&Xs[k][ty * 4];
            float4 b4 = *(const float4*)&Bs[k][tx * 4];
            float ar[4] = {a.x, a.y, a.z, a.w};
            float br[4] = {b4.x, b4.y, b4.z, b4.w};
#pragma unroll
            for (int i = 0; i < 4; i++)
#pragma unroll
                for (int j = 0; j < 4; j++) acc[i][j] = fmaf(ar[i], br[j], acc[i][j]);
        }

        int c0 = cg * 64 + tx * 4;
#pragma unroll
        for (int i = 0; i < 4; i++) {
            int gn = n0 + ty * 4 + i;
            if (gn < NN) {
                float4 o = make_float4(acc[i][0], acc[i][1], acc[i][2], acc[i][3]);
                if (c0 < 128) *(float4*)(g_Hd + (size_t)gn * 128 + c0) = o;
                else          *(float4*)(g_Hs + (size_t)gn * 128 + (c0 - 128)) = o;
            }
        }
    }
}

// ---------------- fused gather+aggregate (2 nodes/block, 4-wide, local scales) --
__global__ __launch_bounds__(256) void k_agg(const float* __restrict__ preb, int layer) {
    int n = blockIdx.x * 2 + (threadIdx.x >> 7);
    int f = threadIdx.x & 127;     // 0..127
    int lo = g_rowptr[n], hi = g_rowptr[n + 1];
    float sum = 0.f, sq = 0.f;
    float mn = INFINITY, mx = -INFINITY;
    int p = lo;
    for (; p + 4 <= hi; p += 4) {
        int i0 = g_csrc[p], i1 = g_csrc[p + 1], i2 = g_csrc[p + 2], i3 = g_csrc[p + 3];
        float v0 = g_Hs[(size_t)i0 * 128 + f];
        float v1 = g_Hs[(size_t)i1 * 128 + f];
        float v2 = g_Hs[(size_t)i2 * 128 + f];
        float v3 = g_Hs[(size_t)i3 * 128 + f];
        sum += (v0 + v1) + (v2 + v3);
        sq  = fmaf(v0, v0, fmaf(v1, v1, fmaf(v2, v2, fmaf(v3, v3, sq))));
        mn = fminf(mn, fminf(fminf(v0, v1), fminf(v2, v3)));
        mx = fmaxf(mx, fmaxf(fmaxf(v0, v1), fmaxf(v2, v3)));
    }
    for (; p < hi; p++) {
        float v = g_Hs[(size_t)g_csrc[p] * 128 + f];
        sum += v; sq = fmaf(v, v, sq);
        mn = fminf(mn, v); mx = fmaxf(mx, v);
    }
    int deg = hi - lo;
    float dc   = fmaxf((float)deg, 1.f);
    float invc = 1.f / dc;
    if (layer == 0 && f == 0) {
        float avg = g_sumlog / (float)NN;
        float ld  = logf(dc + 1.f);
        g_s1[n] = ld / avg;
        g_s2[n] = avg / ld;
    }
    float c = g_Hd[(size_t)n * 128 + f] + preb[f];
    float mean, mnO, mxO, sd;
    if (deg > 0) {
        float ms  = sum * invc;
        float var = sq * invc - ms * ms;
        mean = c + ms; mnO = c + mn; mxO = c + mx;
        sd = sqrtf(fmaxf(var, 0.f) + 1e-5f);
    } else {
        mean = 0.f; mnO = 0.f; mxO = 0.f; sd = sqrtf(1e-5f);
    }
    int tt = f >> 6, ff = f & 63;
    size_t base = (size_t)n * 512 + tt * 256 + ff;
    g_agg[base]       = mean;
    g_agg[base + 64]  = mnO;
    g_agg[base + 128] = mxO;
    g_agg[base + 192] = sd;
}

// ---------------- fused post+lin GEMM (occupancy-tuned: 3 blocks/SM) ------------
#define TSTRIDE 4360   // tower stride in floats (4360 % 32 = 8 -> disjoint banks)
__global__ __launch_bounds__(256, 3) void k_postlin(const float* __restrict__ postW,
                                                    const float* __restrict__ postb,
                                                    const float* __restrict__ linW,
                                                    const float* __restrict__ linb,
                                                    float* __restrict__ outp) {
    __shared__ float A13[2 * TSTRIDE]; // [tower][node(64)][k(68 pad)] — 34880 B
    __shared__ float Ws[64][64];       // weights tile — 16384 B
    int t  = threadIdx.x;
    int n0 = blockIdx.x * 64;
    int tx = t & 15, ty = t >> 4;
    int tc = tx >> 3;                  // tower for this thread's columns
    int abase = tc * TSTRIDE + ty * 4 * 68;   // this thread's 4 node rows

    float acc[4][4];
#pragma unroll
    for (int i = 0; i < 4; i++)
#pragma unroll
        for (int j = 0; j < 4; j++) acc[i][j] = 0.f;

    for (int ci = 0; ci < 13; ci++) {
        int kc = ci * 64;
        // prefetch A source into registers (long-latency g_agg gather)
        float4 va[8];
#pragma unroll
        for (int i = 0; i < 8; i++) {
            int u = t + 256 * i;
            int tw = u >> 10, node = (u >> 4) & 63, kq = u & 15;
            int gn = n0 + node;
            float4 v = make_float4(0.f, 0.f, 0.f, 0.f);
            if (gn < NN) {
                if (ci == 0) {
                    v = *(const float4*)(g_hA + (size_t)gn * 64 + kq * 4);
                } else {
                    int k = kc + kq * 4;
                    int j; float s = 1.f;
                    if (ci < 5)      { j = k - 64; }
                    else if (ci < 9) { j = k - 320; s = g_s1[gn]; }
                    else             { j = k - 576; s = g_s2[gn]; }
                    v = *(const float4*)(g_agg + (size_t)gn * 512 + tw * 256 + j);
                    v.x *= s; v.y *= s; v.z *= s; v.w *= s;
                }
            }
            va[i] = v;
        }
        __syncthreads();
#pragma unroll
        for (int i = 0; i < 8; i++) {
            int u = t + 256 * i;
            int tw = u >> 10, node = (u >> 4) & 63, kq = u & 15;
            *(float4*)&A13[tw * TSTRIDE + node * 68 + kq * 4] = va[i];
        }
        // Ws fill direct from L2-resident postW (no prefetch regs)
#pragma unroll
        for (int i = 0; i < 4; i++) {
            int u = t + 256 * i;
            int kk = u >> 4, cq = u & 15;
            int tw = cq >> 3, g = (cq * 4) & 31;
            ((float4*)Ws)[u] = *(const float4*)(postW + tw * 26624 + (kc + kk) * 32 + g);
        }
        __syncthreads();

#pragma unroll
        for (int kk = 0; kk < 64; kk += 4) {
            float4 ar4[4];
#pragma unroll
            for (int i = 0; i < 4; i++)
                ar4[i] = *(const float4*)&A13[abase + i * 68 + kk];
#pragma unroll
            for (int d = 0; d < 4; d++) {
                float4 b4 = *(const float4*)&Ws[kk + d][tx * 4];
                float br[4] = {b4.x, b4.y, b4.z, b4.w};
#pragma unroll
                for (int i = 0; i < 4; i++) {
                    float av = (&ar4[i].x)[d];
#pragma unroll
                    for (int j = 0; j < 4; j++) acc[i][j] = fmaf(av, br[j], acc[i][j]);
                }
            }
        }
        __syncthreads();
    }

    // -------- stage 2: P-tile -> smem (tower-0 area), multiply by linW --------
    float4 pbias = *(const float4*)(postb + tx * 4);
#pragma unroll
    for (int i = 0; i < 4; i++) {
        int r = (ty * 4 + i) * 68;
        A13[r + tx * 4 + 0] = acc[i][0] + pbias.x;
        A13[r + tx * 4 + 1] = acc[i][1] + pbias.y;
        A13[r + tx * 4 + 2] = acc[i][2] + pbias.z;
        A13[r + tx * 4 + 3] = acc[i][3] + pbias.w;
    }
#pragma unroll
    for (int i = 0; i < 4; i++)
        ((float4*)Ws)[t + 256 * i] = ((const float4*)linW)[t + 256 * i];
    __syncthreads();

    float acc2[4][4];
#pragma unroll
    for (int i = 0; i < 4; i++)
#pragma unroll
        for (int j = 0; j < 4; j++) acc2[i][j] = 0.f;

    int a2base = ty * 4 * 68;
#pragma unroll
    for (int kk = 0; kk < 64; kk += 4) {
        float4 ar4[4];
#pragma unroll
        for (int i = 0; i < 4; i++)
            ar4[i] = *(const float4*)&A13[a2base + i * 68 + kk];
#pragma unroll
        for (int d = 0; d < 4; d++) {
            float4 b4 = *(const float4*)&Ws[kk + d][tx * 4];
            float br[4] = {b4.x, b4.y, b4.z, b4.w};
#pragma unroll
            for (int i = 0; i < 4; i++) {
                float av = (&ar4[i].x)[d];
#pragma unroll
                for (int j = 0; j < 4; j++) acc2[i][j] = fmaf(av, br[j], acc2[i][j]);
            }
        }
    }

    float* target = outp ? outp : g_hB;
    float4 lbias = *(const float4*)(linb + tx * 4);
    float lsum[4] = {0.f, 0.f, 0.f, 0.f};
    float lsq[4]  = {0.f, 0.f, 0.f, 0.f};
#pragma unroll
    for (int i = 0; i < 4; i++) {
        int gn = n0 + ty * 4 + i;
        if (gn < NN) {
            float o0 = acc2[i][0] + lbias.x, o1 = acc2[i][1] + lbias.y;
            float o2 = acc2[i][2] + lbias.z, o3 = acc2[i][3] + lbias.w;
            *(float4*)(target + (size_t)gn * 64 + tx * 4) = make_float4(o0, o1, o2, o3);
            lsum[0] += o0; lsum[1] += o1; lsum[2] += o2; lsum[3] += o3;
            lsq[0] = fmaf(o0, o0, lsq[0]); lsq[1] = fmaf(o1, o1, lsq[1]);
            lsq[2] = fmaf(o2, o2, lsq[2]); lsq[3] = fmaf(o3, o3, lsq[3]);
        }
    }

    if (!outp) {   // fused BN stats (layer 1)
        __syncthreads();
        float* redS = &A13[TSTRIDE];
        float* redQ = &Ws[0][0];
#pragma unroll
        for (int j = 0; j < 4; j++) {
            redS[ty * 68 + tx * 4 + j] = lsum[j];
            redQ[ty * 68 + tx * 4 + j] = lsq[j];
        }
        __syncthreads();
        for (int o = 8; o > 0; o >>= 1) {
            if (ty < o) {
#pragma unroll
                for (int j = 0; j < 4; j++) {
                    redS[ty * 68 + tx * 4 + j] += redS[(ty + o) * 68 + tx * 4 + j];
                    redQ[ty * 68 + tx * 4 + j] += redQ[(ty + o) * 68 + tx * 4 + j];
                }
            }
            __syncthreads();
        }
        if (ty == 0) {
#pragma unroll
            for (int j = 0; j < 4; j++) {
                atomicAdd(&g_bnsum[tx * 4 + j], redS[tx * 4 + j]);
                atomicAdd(&g_bnsq[tx * 4 + j],  redQ[tx * 4 + j]);
            }
        }
    }
}

// ---------------- launch --------------------------------------------------------
extern "C" void kernel_launch(void* const* d_in, const int* in_sizes, int n_in,
                              void* d_out, int out_size) {
    const float* x       = (const float*)d_in[0];
    const float* embed_W = (const float*)d_in[1];
    const float* embed_b = (const float*)d_in[2];
    const float* pre_W1  = (const float*)d_in[3];
    const float* pre_b1  = (const float*)d_in[4];
    const float* post_W1 = (const float*)d_in[5];
    const float* post_b1 = (const float*)d_in[6];
    const float* lin_W1  = (const float*)d_in[7];
    const float* lin_b1  = (const float*)d_in[8];
    const float* bn_g    = (const float*)d_in[9];
    const float* bn_b    = (const float*)d_in[10];
    const float* pre_W2  = (const float*)d_in[11];
    const float* pre_b2  = (const float*)d_in[12];
    const float* post_W2 = (const float*)d_in[13];
    const float* post_b2 = (const float*)d_in[14];
    const float* lin_W2  = (const float*)d_in[15];
    const float* lin_b2  = (const float*)d_in[16];
    const int*   src     = (const int*)d_in[17];
    const int*   dst     = (const int*)d_in[18];
    float* out = (float*)d_out;

    const int GN256 = (NN + 255) / 256;    // 196 = NBLK
    const int GE256 = NE / 256;
    const int GT64  = (NN + 63) / 64;      // 782

    // graph structure (shared by both layers) — parallel 3-phase scan
    k_init<<<GN256, 256>>>();
    k_degree<<<GE256, 256>>>(dst);
    k_blk<<<GN256, 256>>>();
    k_scanblk<<<1, 256>>>();
    k_rowptr<<<GN256, 256>>>();
    k_scatter<<<GE256, 256>>>(src, dst);

    // weight packing (independent of embed inputs)
    k_preB2both<<<128, 256>>>(pre_W1, pre_W2);

    // ---- layer 1 (embed fused with Hd/Hs) ----
    k_embedhds<<<GT64, 256>>>(x, embed_W, embed_b);
    k_agg<<<NN / 2, 256>>>(pre_b1, 0);    // also stores s1/s2
    k_postlin<<<GT64, 256>>>(post_W1, post_b1, lin_W1, lin_b1, nullptr); // + BN stats

    // ---- layer 2 (k_hds1 computes BN scale/shift inline + applies BN+ReLU) ----
    k_hds1<<<GT64, 256>>>(bn_g, bn_b);
    k_agg<<<NN / 2, 256>>>(pre_b2, 1);
    k_postlin<<<GT64, 256>>>(post_W2, post_b2, lin_W2, lin_b2, out);
}